// round 1
// baseline (speedup 1.0000x reference)
#include <cuda_runtime.h>
#include <cuda_bf16.h>

// Problem constants
#define BB 2
#define CC 256
#define NN 4096          // 64*64
#define DD 768           // 3*CC
#define IN 32            // inter

// Scratch (static device globals; no allocation)
__device__ float d_M[BB][DD][NN];       // [x ; avgpool3(x) ; avgpool5(x)], unscaled
__device__ float d_GX[BB][NN][IN];      // g_x transposed: [b][n][i]
__device__ float d_S[3][BB][CC];        // per-channel plane sums (variant,b,c)
__device__ float d_sqrtV[BB][3];        // sqrt(softmax weights)

// ---------------- helpers: packed f32x2 FMA ----------------
__device__ __forceinline__ void fma2(unsigned long long& d, unsigned long long a, unsigned long long b) {
    asm("fma.rn.f32x2 %0, %1, %2, %0;" : "+l"(d) : "l"(a), "l"(b));
}
__device__ __forceinline__ unsigned long long pack2(float x) {
    unsigned long long r; asm("mov.b64 %0, {%1, %1};" : "=l"(r) : "f"(x)); return r;
}
__device__ __forceinline__ float2 unpack2(unsigned long long v) {
    float2 f; asm("mov.b64 {%0, %1}, %2;" : "=f"(f.x), "=f"(f.y) : "l"(v)); return f;
}
__device__ __forceinline__ float redmax16(float v) {
    v = fmaxf(v, __shfl_xor_sync(0xffffffffu, v, 1));
    v = fmaxf(v, __shfl_xor_sync(0xffffffffu, v, 2));
    v = fmaxf(v, __shfl_xor_sync(0xffffffffu, v, 4));
    v = fmaxf(v, __shfl_xor_sync(0xffffffffu, v, 8));
    return v;
}
__device__ __forceinline__ float redsum16(float v) {
    v += __shfl_xor_sync(0xffffffffu, v, 1);
    v += __shfl_xor_sync(0xffffffffu, v, 2);
    v += __shfl_xor_sync(0xffffffffu, v, 4);
    v += __shfl_xor_sync(0xffffffffu, v, 8);
    return v;
}

// ---------------- kernel 1: pooling + build M + channel sums ----------------
// grid (256, 2), block 128. One (b,c) plane per block.
__global__ void pool_kernel(const float* __restrict__ x) {
    const int c = blockIdx.x, b = blockIdx.y;
    const float* xp = x + ((size_t)(b * CC + c)) * NN;
    __shared__ float xs[64][64];
    __shared__ float h3[64][64];
    __shared__ float h5[64][64];
    const int t = threadIdx.x;

    for (int p = t; p < NN; p += 128) xs[p >> 6][p & 63] = xp[p];
    __syncthreads();
    for (int p = t; p < NN; p += 128) {
        int h = p >> 6, w = p & 63;
        float c0 = xs[h][w];
        float l1 = (w > 0)  ? xs[h][w - 1] : 0.f;
        float r1 = (w < 63) ? xs[h][w + 1] : 0.f;
        float l2 = (w > 1)  ? xs[h][w - 2] : 0.f;
        float r2 = (w < 62) ? xs[h][w + 2] : 0.f;
        h3[h][w] = l1 + c0 + r1;
        h5[h][w] = l2 + l1 + c0 + r1 + r2;
    }
    __syncthreads();
    float s1 = 0.f, s3 = 0.f, s5 = 0.f;
    float* Mx = &d_M[b][c][0];
    float* M3 = &d_M[b][CC + c][0];
    float* M5 = &d_M[b][2 * CC + c][0];
    for (int p = t; p < NN; p += 128) {
        int h = p >> 6, w = p & 63;
        float v0 = xs[h][w];
        float u1 = (h > 0)  ? h3[h - 1][w] : 0.f;
        float dn1 = (h < 63) ? h3[h + 1][w] : 0.f;
        float u2 = (h > 1)  ? h5[h - 2][w] : 0.f;
        float dn2 = (h < 62) ? h5[h + 2][w] : 0.f;
        float u1b = (h > 0)  ? h5[h - 1][w] : 0.f;
        float dn1b = (h < 63) ? h5[h + 1][w] : 0.f;
        float p3 = (u1 + h3[h][w] + dn1) * (1.f / 9.f);
        float p5 = (u2 + u1b + h5[h][w] + dn1b + dn2) * (1.f / 25.f);
        Mx[p] = v0; M3[p] = p3; M5[p] = p5;
        s1 += v0; s3 += p3; s5 += p5;
    }
    __syncthreads();
    float* r1 = &xs[0][0];
    float* r3 = &h3[0][0];
    float* r5 = &h5[0][0];
    r1[t] = s1; r3[t] = s3; r5[t] = s5;
    __syncthreads();
    for (int off = 64; off > 0; off >>= 1) {
        if (t < off) { r1[t] += r1[t + off]; r3[t] += r3[t + off]; r5[t] += r5[t + off]; }
        __syncthreads();
    }
    if (t == 0) {
        d_S[0][b][c] = r1[0];
        d_S[1][b][c] = r3[0];
        d_S[2][b][c] = r5[0];
    }
}

// ---------------- kernel 2: tiny V computation ----------------
__global__ void vcalc_kernel(const float* __restrict__ W1, const float* __restrict__ W2) {
    __shared__ float m[BB][3];
    const int t = threadIdx.x;
    if (t < 6) {
        int k = t % 3, b = t / 3;
        float s = 0.f;
        for (int c = 0; c < CC; c++) { float v = d_S[k][b][c]; s += v * v; }
        m[b][k] = s * (1.f / ((float)NN * (float)NN));
    }
    __syncthreads();
    if (t < BB) {
        int b = t;
        float h[16];
        #pragma unroll
        for (int i = 0; i < 16; i++)
            h[i] = W1[i * 3 + 0] * m[b][0] + W1[i * 3 + 1] * m[b][1] + W1[i * 3 + 2] * m[b][2];
        float o[3];
        #pragma unroll
        for (int j = 0; j < 3; j++) {
            float s = 0.f;
            #pragma unroll
            for (int i = 0; i < 16; i++) s += W2[j * 16 + i] * h[i];
            o[j] = s;
        }
        float mx = fmaxf(o[0], fmaxf(o[1], o[2]));
        float e0 = expf(o[0] - mx), e1 = expf(o[1] - mx), e2 = expf(o[2] - mx);
        float inv = 1.f / (e0 + e1 + e2);
        d_sqrtV[b][0] = sqrtf(e0 * inv);
        d_sqrtV[b][1] = sqrtf(e1 * inv);
        d_sqrtV[b][2] = sqrtf(e2 * inv);
    }
}

// ---------------- kernel 3: g_x = (Wg @ x)^T ----------------
// grid (32, 2), block 256. 128 n's per block.
__global__ void gx_kernel(const float* __restrict__ x, const float* __restrict__ Wg) {
    const int b = blockIdx.y;
    const int n0 = blockIdx.x * 128;
    __shared__ float xs[32][128];
    __shared__ float Wgs[32][32]; // [cc][i]
    const int t = threadIdx.x;
    const int i = t & 31, ng = t >> 5;
    float acc[16];
    #pragma unroll
    for (int j = 0; j < 16; j++) acc[j] = 0.f;
    const float* xb = x + (size_t)b * CC * NN;
    for (int c0 = 0; c0 < CC; c0 += 32) {
        for (int e = t; e < 32 * 128; e += 256)
            xs[e >> 7][e & 127] = xb[(size_t)(c0 + (e >> 7)) * NN + n0 + (e & 127)];
        for (int e = t; e < 1024; e += 256) {
            int cc = e & 31, ii = e >> 5;
            Wgs[cc][ii] = Wg[ii * CC + c0 + cc];
        }
        __syncthreads();
        #pragma unroll 8
        for (int cc = 0; cc < 32; cc++) {
            float w = Wgs[cc][i];
            #pragma unroll
            for (int j = 0; j < 16; j++) acc[j] += w * xs[cc][ng * 16 + j];
        }
        __syncthreads();
    }
    #pragma unroll
    for (int j = 0; j < 16; j++) d_GX[b][n0 + ng * 16 + j][i] = acc[j];
}

// ---------------- kernel 4: fused flash attention + Ww conv + residual ----------------
// grid (64, 2), block 256. TM=64 query rows per block, TN=128 key cols per tile.
// Thread (tr,tc): tr=tid/16 -> 4 rows, tc=tid%16 -> 8 cols (as 4 f32x2 pairs).
__global__ __launch_bounds__(256, 1) void flash_kernel(const float* __restrict__ x,
                                                       const float* __restrict__ Ww,
                                                       float* __restrict__ out) {
    __shared__ __align__(16) char sm[49152];
    float (*Ps)[128] = (float (*)[128])sm;                 // 32768 B
    float (*Qs)[68]  = (float (*)[68])(sm + 32768);        // 4352 B   (union A)
    float (*Ks)[132] = (float (*)[132])(sm + 37120);       // 8448 B   (union A)
    float (*Vs)[32]  = (float (*)[32])(sm + 32768);        // 16384 B  (union A)
    float (*ysT)[64] = (float (*)[64])(sm + 32768);        // 8192 B   (epilogue)
    float (*Ws)[32]  = (float (*)[32])sm;                  // 32768 B  (epilogue, over Ps)

    const int b = blockIdx.y;
    const int i0 = blockIdx.x * 64;
    const int tid = threadIdx.x;
    const int tr = tid >> 4, tc = tid & 15;

    float scv[3];
    scv[0] = d_sqrtV[b][0]; scv[1] = d_sqrtV[b][1]; scv[2] = d_sqrtV[b][2];

    float mrow[4], lrow[4], O[4][2];
    #pragma unroll
    for (int a = 0; a < 4; a++) { mrow[a] = -1e30f; lrow[a] = 0.f; O[a][0] = 0.f; O[a][1] = 0.f; }

    const int qrow = tid >> 4;          // 0..15
    const int qcol = (tid & 15) << 2;   // 0..60

    for (int jt = 0; jt < 32; jt++) {
        const int j0 = jt << 7;
        unsigned long long acc[4][4];
        #pragma unroll
        for (int a = 0; a < 4; a++)
            #pragma unroll
            for (int p = 0; p < 4; p++) acc[a][p] = 0ull;

        #pragma unroll 1
        for (int d0 = 0; d0 < DD; d0 += 16) {
            __syncthreads();
            {
                int dr = d0 + qrow;
                float s = scv[dr >> 8];
                float4 q = *(const float4*)&d_M[b][dr][i0 + qcol];
                q.x *= s; q.y *= s; q.z *= s; q.w *= s;
                *(float4*)&Qs[qrow][qcol] = q;
                #pragma unroll
                for (int p = 0; p < 2; p++) {
                    int idx = (p << 8) + tid;
                    int krow = idx >> 5, kcol = (idx & 31) << 2;
                    int drk = d0 + krow;
                    float sk = scv[drk >> 8];
                    float4 kv = *(const float4*)&d_M[b][drk][j0 + kcol];
                    kv.x *= sk; kv.y *= sk; kv.z *= sk; kv.w *= sk;
                    *(float4*)&Ks[krow][kcol] = kv;
                }
            }
            __syncthreads();
            #pragma unroll
            for (int k = 0; k < 16; k++) {
                float4 q4 = *(const float4*)&Qs[k][tr << 2];
                ulonglong2 ka = *(const ulonglong2*)&Ks[k][tc << 3];
                ulonglong2 kb = *(const ulonglong2*)&Ks[k][(tc << 3) + 4];
                unsigned long long qa = pack2(q4.x), qb = pack2(q4.y), qc = pack2(q4.z), qd = pack2(q4.w);
                fma2(acc[0][0], qa, ka.x); fma2(acc[0][1], qa, ka.y); fma2(acc[0][2], qa, kb.x); fma2(acc[0][3], qa, kb.y);
                fma2(acc[1][0], qb, ka.x); fma2(acc[1][1], qb, ka.y); fma2(acc[1][2], qb, kb.x); fma2(acc[1][3], qb, kb.y);
                fma2(acc[2][0], qc, ka.x); fma2(acc[2][1], qc, ka.y); fma2(acc[2][2], qc, kb.x); fma2(acc[2][3], qc, kb.y);
                fma2(acc[3][0], qd, ka.x); fma2(acc[3][1], qd, ka.y); fma2(acc[3][2], qd, kb.x); fma2(acc[3][3], qd, kb.y);
            }
        }
        __syncthreads();   // all Ks reads done before Vs overwrites the region

        // online softmax on the 4x8 register tile
        float S[4][8];
        #pragma unroll
        for (int a = 0; a < 4; a++)
            #pragma unroll
            for (int p = 0; p < 4; p++) {
                float2 f = unpack2(acc[a][p]);
                S[a][2 * p] = f.x; S[a][2 * p + 1] = f.y;
            }
        #pragma unroll
        for (int a = 0; a < 4; a++) {
            float tm = S[a][0];
            #pragma unroll
            for (int q = 1; q < 8; q++) tm = fmaxf(tm, S[a][q]);
            tm = redmax16(tm);
            float mnew = fmaxf(mrow[a], tm);
            float scale = __expf(mrow[a] - mnew);
            mrow[a] = mnew;
            float rs = 0.f;
            #pragma unroll
            for (int q = 0; q < 8; q++) { float e = __expf(S[a][q] - mnew); S[a][q] = e; rs += e; }
            rs = redsum16(rs);
            lrow[a] = lrow[a] * scale + rs;
            O[a][0] *= scale; O[a][1] *= scale;
            *(float4*)&Ps[(tr << 2) + a][tc << 3]       = make_float4(S[a][0], S[a][1], S[a][2], S[a][3]);
            *(float4*)&Ps[(tr << 2) + a][(tc << 3) + 4] = make_float4(S[a][4], S[a][5], S[a][6], S[a][7]);
        }
        // load V tile (g_x rows j0..j0+127)
        #pragma unroll
        for (int p = 0; p < 16; p++) {
            int e = (p << 8) + tid;
            Vs[e >> 5][e & 31] = d_GX[b][j0 + (e >> 5)][e & 31];
        }
        __syncthreads();
        // P @ V
        #pragma unroll 4
        for (int j = 0; j < 128; j++) {
            float2 v = *(const float2*)&Vs[j][tc << 1];
            #pragma unroll
            for (int a = 0; a < 4; a++) {
                float pv = Ps[(tr << 2) + a][j];
                O[a][0] += pv * v.x;
                O[a][1] += pv * v.y;
            }
        }
    }
    __syncthreads();   // PV reads done before epilogue overwrites smem

    // y = O / l  ->  ysT[i][r]  (transposed for conflict-free epilogue reads)
    #pragma unroll
    for (int a = 0; a < 4; a++) {
        float invl = 1.f / lrow[a];
        ysT[(tc << 1)][(tr << 2) + a]     = O[a][0] * invl;
        ysT[(tc << 1) + 1][(tr << 2) + a] = O[a][1] * invl;
    }
    // load Ww into smem (over Ps region)
    #pragma unroll
    for (int p = 0; p < 32; p++) {
        int e = (p << 8) + tid;
        Ws[e >> 5][e & 31] = Ww[e];
    }
    __syncthreads();

    // z[b,c,n] = sum_i Ww[c,i] * y[n,i] + x[b,c,n]
    const int r = tid & 63;
    const int cg = tid >> 6;
    float yreg[32];
    #pragma unroll
    for (int i = 0; i < 32; i++) yreg[i] = ysT[i][r];
    const float* xb = x + (size_t)b * CC * NN;
    float* ob = out + (size_t)b * CC * NN;
    #pragma unroll 4
    for (int k = 0; k < 64; k++) {
        int c = (cg << 6) + k;
        float s = 0.f;
        #pragma unroll
        for (int i = 0; i < 32; i++) s += Ws[c][i] * yreg[i];
        ob[(size_t)c * NN + i0 + r] = s + xb[(size_t)c * NN + i0 + r];
    }
}

extern "C" void kernel_launch(void* const* d_in, const int* in_sizes, int n_in,
                              void* d_out, int out_size) {
    const float* x  = (const float*)d_in[0];
    const float* Wg = (const float*)d_in[1];
    const float* Ww = (const float*)d_in[2];
    const float* W1 = (const float*)d_in[3];
    const float* W2 = (const float*)d_in[4];
    float* out = (float*)d_out;

    pool_kernel<<<dim3(CC, BB), 128>>>(x);
    vcalc_kernel<<<1, 64>>>(W1, W2);
    gx_kernel<<<dim3(NN / 128, BB), 256>>>(x, Wg);
    flash_kernel<<<dim3(NN / 64, BB), 256>>>(x, Ww, out);
}

// round 2
// speedup vs baseline: 1.7083x; 1.7083x over previous
#include <cuda_runtime.h>
#include <cuda_bf16.h>

// Problem constants
#define BB 2
#define CC 256
#define NN 4096          // 64*64
#define DD 768           // 3*CC
#define IN 32            // inter

#define TM 64            // query rows per block
#define TN 256           // key cols per tile
#define KB 32            // k-chunk depth

// Scratch (static device globals; no allocation)
__device__ float d_M[BB][DD][NN];       // [x ; avgpool3(x) ; avgpool5(x)] -> scaled by sqrtV
__device__ float d_GX[BB][NN][IN];      // g_x transposed: [b][n][i]
__device__ float d_S[3][BB][CC];        // per-channel plane sums (variant,b,c)
__device__ float d_sqrtV[BB][3];        // sqrt(softmax weights)

// ---------------- helpers ----------------
__device__ __forceinline__ void fma2(unsigned long long& d, unsigned long long a, unsigned long long b) {
    asm("fma.rn.f32x2 %0, %1, %2, %0;" : "+l"(d) : "l"(a), "l"(b));
}
__device__ __forceinline__ unsigned long long pack2(float x) {
    unsigned long long r; asm("mov.b64 %0, {%1, %1};" : "=l"(r) : "f"(x)); return r;
}
__device__ __forceinline__ float2 unpack2(unsigned long long v) {
    float2 f; asm("mov.b64 {%0, %1}, %2;" : "=f"(f.x), "=f"(f.y) : "l"(v)); return f;
}
__device__ __forceinline__ float redmax32(float v) {
    #pragma unroll
    for (int o = 16; o > 0; o >>= 1) v = fmaxf(v, __shfl_xor_sync(0xffffffffu, v, o));
    return v;
}
__device__ __forceinline__ float redsum32(float v) {
    #pragma unroll
    for (int o = 16; o > 0; o >>= 1) v += __shfl_xor_sync(0xffffffffu, v, o);
    return v;
}

// ---------------- kernel 1: pooling + build M + channel sums ----------------
__global__ void pool_kernel(const float* __restrict__ x) {
    const int c = blockIdx.x, b = blockIdx.y;
    const float* xp = x + ((size_t)(b * CC + c)) * NN;
    __shared__ float xs[64][64];
    __shared__ float h3[64][64];
    __shared__ float h5[64][64];
    const int t = threadIdx.x;

    for (int p = t; p < NN; p += 128) xs[p >> 6][p & 63] = xp[p];
    __syncthreads();
    for (int p = t; p < NN; p += 128) {
        int h = p >> 6, w = p & 63;
        float c0 = xs[h][w];
        float l1 = (w > 0)  ? xs[h][w - 1] : 0.f;
        float r1 = (w < 63) ? xs[h][w + 1] : 0.f;
        float l2 = (w > 1)  ? xs[h][w - 2] : 0.f;
        float r2 = (w < 62) ? xs[h][w + 2] : 0.f;
        h3[h][w] = l1 + c0 + r1;
        h5[h][w] = l2 + l1 + c0 + r1 + r2;
    }
    __syncthreads();
    float s1 = 0.f, s3 = 0.f, s5 = 0.f;
    float* Mx = &d_M[b][c][0];
    float* M3 = &d_M[b][CC + c][0];
    float* M5 = &d_M[b][2 * CC + c][0];
    for (int p = t; p < NN; p += 128) {
        int h = p >> 6, w = p & 63;
        float v0 = xs[h][w];
        float u1 = (h > 0)  ? h3[h - 1][w] : 0.f;
        float dn1 = (h < 63) ? h3[h + 1][w] : 0.f;
        float u2 = (h > 1)  ? h5[h - 2][w] : 0.f;
        float dn2 = (h < 62) ? h5[h + 2][w] : 0.f;
        float u1b = (h > 0)  ? h5[h - 1][w] : 0.f;
        float dn1b = (h < 63) ? h5[h + 1][w] : 0.f;
        float p3 = (u1 + h3[h][w] + dn1) * (1.f / 9.f);
        float p5 = (u2 + u1b + h5[h][w] + dn1b + dn2) * (1.f / 25.f);
        Mx[p] = v0; M3[p] = p3; M5[p] = p5;
        s1 += v0; s3 += p3; s5 += p5;
    }
    __syncthreads();
    float* r1 = &xs[0][0];
    float* r3 = &h3[0][0];
    float* r5 = &h5[0][0];
    r1[t] = s1; r3[t] = s3; r5[t] = s5;
    __syncthreads();
    for (int off = 64; off > 0; off >>= 1) {
        if (t < off) { r1[t] += r1[t + off]; r3[t] += r3[t + off]; r5[t] += r5[t + off]; }
        __syncthreads();
    }
    if (t == 0) {
        d_S[0][b][c] = r1[0];
        d_S[1][b][c] = r3[0];
        d_S[2][b][c] = r5[0];
    }
}

// ---------------- kernel 2: tiny V computation ----------------
__global__ void vcalc_kernel(const float* __restrict__ W1, const float* __restrict__ W2) {
    __shared__ float m[BB][3];
    const int t = threadIdx.x;
    if (t < 6) {
        int k = t % 3, b = t / 3;
        float s = 0.f;
        for (int c = 0; c < CC; c++) { float v = d_S[k][b][c]; s += v * v; }
        m[b][k] = s * (1.f / ((float)NN * (float)NN));
    }
    __syncthreads();
    if (t < BB) {
        int b = t;
        float h[16];
        #pragma unroll
        for (int i = 0; i < 16; i++)
            h[i] = W1[i * 3 + 0] * m[b][0] + W1[i * 3 + 1] * m[b][1] + W1[i * 3 + 2] * m[b][2];
        float o[3];
        #pragma unroll
        for (int j = 0; j < 3; j++) {
            float s = 0.f;
            #pragma unroll
            for (int i = 0; i < 16; i++) s += W2[j * 16 + i] * h[i];
            o[j] = s;
        }
        float mx = fmaxf(o[0], fmaxf(o[1], o[2]));
        float e0 = expf(o[0] - mx), e1 = expf(o[1] - mx), e2 = expf(o[2] - mx);
        float inv = 1.f / (e0 + e1 + e2);
        d_sqrtV[b][0] = sqrtf(e0 * inv);
        d_sqrtV[b][1] = sqrtf(e1 * inv);
        d_sqrtV[b][2] = sqrtf(e2 * inv);
    }
}

// ---------------- kernel 2b: scale M in place by sqrtV ----------------
__global__ void scale_kernel() {
    int f = blockIdx.x * blockDim.x + threadIdx.x;  // float4 index
    // total f4 = BB*DD*NN/4 = 1572864; grid sized exactly
    int row = f >> 10;            // NN/4 = 1024 f4 per row
    int b = row / DD, dr = row - b * DD;
    float s = d_sqrtV[b][dr >> 8];
    float4* p = (float4*)&d_M[0][0][0];
    float4 v = p[f];
    v.x *= s; v.y *= s; v.z *= s; v.w *= s;
    p[f] = v;
}

// ---------------- kernel 3: g_x = (Wg @ x)^T ----------------
__global__ void gx_kernel(const float* __restrict__ x, const float* __restrict__ Wg) {
    const int b = blockIdx.y;
    const int n0 = blockIdx.x * 128;
    __shared__ float xs[32][128];
    __shared__ float Wgs[32][32]; // [cc][i]
    const int t = threadIdx.x;
    const int i = t & 31, ng = t >> 5;
    float acc[16];
    #pragma unroll
    for (int j = 0; j < 16; j++) acc[j] = 0.f;
    const float* xb = x + (size_t)b * CC * NN;
    for (int c0 = 0; c0 < CC; c0 += 32) {
        for (int e = t; e < 32 * 128; e += 256)
            xs[e >> 7][e & 127] = xb[(size_t)(c0 + (e >> 7)) * NN + n0 + (e & 127)];
        for (int e = t; e < 1024; e += 256) {
            int cc = e & 31, ii = e >> 5;
            Wgs[cc][ii] = Wg[ii * CC + c0 + cc];
        }
        __syncthreads();
        #pragma unroll 8
        for (int cc = 0; cc < 32; cc++) {
            float w = Wgs[cc][i];
            #pragma unroll
            for (int j = 0; j < 16; j++) acc[j] += w * xs[cc][ng * 16 + j];
        }
        __syncthreads();
    }
    #pragma unroll
    for (int j = 0; j < 16; j++) d_GX[b][n0 + ng * 16 + j][i] = acc[j];
}

// ---------------- kernel 4: fused flash attention + Ww conv + residual ----------------
// grid (64, 2), block 256. TM=64 rows, TN=256 cols/tile, 8x8 register tile.
// warp = tid>>5 owns rows warp*8..+7; lane = tid&31 owns cols lane*8..+7.
__global__ __launch_bounds__(256, 1) void flash2_kernel(const float* __restrict__ x,
                                                        const float* __restrict__ Ww,
                                                        float* __restrict__ out) {
    extern __shared__ __align__(16) float sm[];
    float (*Ps)[TN] = (float (*)[TN])sm;                        // 64*256   = 16384 f
    float (*Vs)[IN] = (float (*)[IN])(sm + TM * TN);            // 256*32   = 8192 f
    float (*Qs)[TM] = (float (*)[TM])(sm + TM * TN + TN * IN);  // 32*64    = 2048 f
    float (*Ks)[TN] = (float (*)[TN])(sm + TM * TN + TN * IN + KB * TM); // 32*256 = 8192 f
    // epilogue aliases:
    float (*Ws)[IN]  = (float (*)[IN])sm;                       // 256*32 over Ps
    float (*ysT)[65] = (float (*)[65])(sm + TM * TN);           // 32*65 over Vs

    const int b = blockIdx.y;
    const int i0 = blockIdx.x * TM;
    const int tid = threadIdx.x;
    const int warp = tid >> 5, lane = tid & 31;

    float mrow[8], lrow[8], Oc[8];
    #pragma unroll
    for (int a = 0; a < 8; a++) { mrow[a] = -1e30f; lrow[a] = 0.f; Oc[a] = 0.f; }

    for (int jt = 0; jt < NN / TN; jt++) {
        const int j0 = jt * TN;
        unsigned long long acc[8][4];
        #pragma unroll
        for (int a = 0; a < 8; a++)
            #pragma unroll
            for (int p = 0; p < 4; p++) acc[a][p] = 0ull;

        #pragma unroll 1
        for (int kc = 0; kc < DD / KB; kc++) {
            const int d0 = kc * KB;
            __syncthreads();
            // load Q chunk: 32x64 = 512 float4
            #pragma unroll
            for (int p = 0; p < 2; p++) {
                int e = (p << 8) + tid;
                int r = e >> 4, c = (e & 15) << 2;
                *(float4*)&Qs[r][c] = *(const float4*)&d_M[b][d0 + r][i0 + c];
            }
            // load K chunk: 32x256 = 2048 float4
            #pragma unroll
            for (int p = 0; p < 8; p++) {
                int e = (p << 8) + tid;
                int r = e >> 6, c = (e & 63) << 2;
                *(float4*)&Ks[r][c] = *(const float4*)&d_M[b][d0 + r][j0 + c];
            }
            __syncthreads();
            #pragma unroll 8
            for (int k = 0; k < KB; k++) {
                float4 qa = *(const float4*)&Qs[k][warp << 3];
                float4 qb = *(const float4*)&Qs[k][(warp << 3) + 4];
                ulonglong2 k0 = *(const ulonglong2*)&Ks[k][lane << 3];
                ulonglong2 k1 = *(const ulonglong2*)&Ks[k][(lane << 3) + 4];
                unsigned long long q;
                q = pack2(qa.x); fma2(acc[0][0], q, k0.x); fma2(acc[0][1], q, k0.y); fma2(acc[0][2], q, k1.x); fma2(acc[0][3], q, k1.y);
                q = pack2(qa.y); fma2(acc[1][0], q, k0.x); fma2(acc[1][1], q, k0.y); fma2(acc[1][2], q, k1.x); fma2(acc[1][3], q, k1.y);
                q = pack2(qa.z); fma2(acc[2][0], q, k0.x); fma2(acc[2][1], q, k0.y); fma2(acc[2][2], q, k1.x); fma2(acc[2][3], q, k1.y);
                q = pack2(qa.w); fma2(acc[3][0], q, k0.x); fma2(acc[3][1], q, k0.y); fma2(acc[3][2], q, k1.x); fma2(acc[3][3], q, k1.y);
                q = pack2(qb.x); fma2(acc[4][0], q, k0.x); fma2(acc[4][1], q, k0.y); fma2(acc[4][2], q, k1.x); fma2(acc[4][3], q, k1.y);
                q = pack2(qb.y); fma2(acc[5][0], q, k0.x); fma2(acc[5][1], q, k0.y); fma2(acc[5][2], q, k1.x); fma2(acc[5][3], q, k1.y);
                q = pack2(qb.z); fma2(acc[6][0], q, k0.x); fma2(acc[6][1], q, k0.y); fma2(acc[6][2], q, k1.x); fma2(acc[6][3], q, k1.y);
                q = pack2(qb.w); fma2(acc[7][0], q, k0.x); fma2(acc[7][1], q, k0.y); fma2(acc[7][2], q, k1.x); fma2(acc[7][3], q, k1.y);
            }
        }

        // online softmax on the 8x8 register tile (warp-wide rows)
        #pragma unroll
        for (int a = 0; a < 8; a++) {
            float S[8];
            #pragma unroll
            for (int p = 0; p < 4; p++) {
                float2 f = unpack2(acc[a][p]);
                S[2 * p] = f.x; S[2 * p + 1] = f.y;
            }
            float tm = S[0];
            #pragma unroll
            for (int q = 1; q < 8; q++) tm = fmaxf(tm, S[q]);
            tm = redmax32(tm);
            float mnew = fmaxf(mrow[a], tm);
            float scale = __expf(mrow[a] - mnew);
            mrow[a] = mnew;
            float rs = 0.f;
            #pragma unroll
            for (int q = 0; q < 8; q++) { float e = __expf(S[q] - mnew); S[q] = e; rs += e; }
            rs = redsum32(rs);
            lrow[a] = lrow[a] * scale + rs;
            Oc[a] *= scale;
            *(float4*)&Ps[(warp << 3) + a][lane << 3]       = make_float4(S[0], S[1], S[2], S[3]);
            *(float4*)&Ps[(warp << 3) + a][(lane << 3) + 4] = make_float4(S[4], S[5], S[6], S[7]);
        }
        // load V tile: 256x32 = 2048 float4
        #pragma unroll
        for (int p = 0; p < 8; p++) {
            int e = (p << 8) + tid;
            int r = e >> 3, c = (e & 7) << 2;
            *(float4*)&Vs[r][c] = *(const float4*)&d_GX[b][j0 + r][c];
        }
        __syncthreads();
        // P @ V: O[row=warp*8+a][col=lane] += sum_j Ps[row][j] * Vs[j][lane]
        #pragma unroll 2
        for (int j = 0; j < TN; j += 4) {
            float v0 = Vs[j][lane], v1 = Vs[j + 1][lane], v2 = Vs[j + 2][lane], v3 = Vs[j + 3][lane];
            #pragma unroll
            for (int a = 0; a < 8; a++) {
                float4 ps = *(const float4*)&Ps[(warp << 3) + a][j];
                Oc[a] += ps.x * v0 + ps.y * v1 + ps.z * v2 + ps.w * v3;
            }
        }
        // next jt's first __syncthreads (top of kc loop) protects Ps/Vs reuse
    }
    __syncthreads();   // PV reads done before epilogue overwrites smem

    // y^T into smem: ysT[i][r]
    #pragma unroll
    for (int a = 0; a < 8; a++) {
        float invl = 1.f / lrow[a];
        ysT[lane][(warp << 3) + a] = Oc[a] * invl;
    }
    // Ww into smem (over Ps region)
    #pragma unroll
    for (int p = 0; p < 32; p++) {
        int e = (p << 8) + tid;
        Ws[e >> 5][e & 31] = Ww[e];
    }
    __syncthreads();

    // z[b,c,i0+r] = sum_i Ww[c,i] * y[r,i] + x[b,c,i0+r]
    const int r = tid & 63;
    const int cg = tid >> 6;
    float yreg[IN];
    #pragma unroll
    for (int i = 0; i < IN; i++) yreg[i] = ysT[i][r];
    const float* xb = x + (size_t)b * CC * NN;
    float* ob = out + (size_t)b * CC * NN;
    #pragma unroll 4
    for (int k = 0; k < 64; k++) {
        int c = (cg << 6) + k;
        float s = 0.f;
        #pragma unroll
        for (int i = 0; i < IN; i++) s += Ws[c][i] * yreg[i];
        ob[(size_t)c * NN + i0 + r] = s + xb[(size_t)c * NN + i0 + r];
    }
}

extern "C" void kernel_launch(void* const* d_in, const int* in_sizes, int n_in,
                              void* d_out, int out_size) {
    const float* x  = (const float*)d_in[0];
    const float* Wg = (const float*)d_in[1];
    const float* Ww = (const float*)d_in[2];
    const float* W1 = (const float*)d_in[3];
    const float* W2 = (const float*)d_in[4];
    float* out = (float*)d_out;

    const int FLASH_SMEM = (TM * TN + TN * IN + KB * TM + KB * TN) * 4;  // 139264 B
    static int configured = 0;
    if (!configured) {
        cudaFuncSetAttribute(flash2_kernel, cudaFuncAttributeMaxDynamicSharedMemorySize, FLASH_SMEM);
        configured = 1;
    }

    pool_kernel<<<dim3(CC, BB), 128>>>(x);
    vcalc_kernel<<<1, 64>>>(W1, W2);
    scale_kernel<<<(BB * DD * NN / 4) / 256, 256>>>();
    gx_kernel<<<dim3(NN / 128, BB), 256>>>(x, Wg);
    flash2_kernel<<<dim3(NN / TM, BB), 256, FLASH_SMEM>>>(x, Ww, out);
}

// round 4
// speedup vs baseline: 8.5206x; 4.9879x over previous
#include <cuda_runtime.h>
#include <cuda_bf16.h>
#include <cuda_fp16.h>
#include <cstdint>

// Problem constants
#define BB 2
#define CC 256
#define NN 4096          // 64*64
#define DD 768           // 3*CC
#define IN 32            // inter

// Flash tiling
#define TMQ 64           // q rows per block
#define TNK 256          // keys per j-tile
#define KC 64            // feature chunk (=128B bf16 row)
#define NCH (DD / KC)    // 12
#define NJT (NN / TNK)   // 16

// SMEM layout (bytes)
#define STAGE_BYTES 40960      // Q tile 8192 + K tile 32768
#define KOFF 8192
#define PS_OFF  81920          // fp16 P [64][272]  (pitch 544B)
#define PS_PITCH 544
#define VTS_OFF 116736         // fp16 VT [32][272] (pitch 544B)
#define VT_PITCH 544
#define PM_OFF  134144         // fp32 [2][64]
#define PSUM_OFF 134656        // fp32 [2][64]
#define MR_OFF  135168         // fp32 [64]
#define LR_OFF  135424         // fp32 [64]
#define SCR_OFF 135680         // fp32 [64]
#define FLASH_SMEM 135936
#define YST_OFF PS_OFF         // epilogue fp32 [32][68] aliases PS
#define WS_OFF  0              // epilogue fp32 [256][32] aliases stage0

// Scratch (static device globals; no allocation)
__device__ float d_M[BB][DD][NN];                         // feature-major fp32 (pool output)
__device__ __align__(16) __nv_bfloat16 d_Mt[BB][NN][DD];  // token-major, scaled, bf16
__device__ __align__(16) __half d_GXT[BB][IN][NN];        // g_x as [b][i][n], fp16
__device__ float d_S[3][BB][CC];
__device__ float d_sqrtV[BB][3];

// ---------------- helpers ----------------
__device__ __forceinline__ uint32_t smem_u32(const void* p) {
    uint32_t a;
    asm("{ .reg .u64 t; cvta.to.shared.u64 t, %1; cvt.u32.u64 %0, t; }" : "=r"(a) : "l"(p));
    return a;
}
__device__ __forceinline__ uint32_t sw128(uint32_t bo) { return bo ^ ((bo >> 3) & 0x70); }

__device__ __forceinline__ void cpa16(uint32_t dst, const void* src) {
    asm volatile("cp.async.cg.shared.global [%0], [%1], 16;" :: "r"(dst), "l"(src));
}
__device__ __forceinline__ void cp_commit() { asm volatile("cp.async.commit_group;"); }
__device__ __forceinline__ void cp_wait1() { asm volatile("cp.async.wait_group 1;"); }
__device__ __forceinline__ void cp_wait0() { asm volatile("cp.async.wait_group 0;"); }

__device__ __forceinline__ void ldsm4(uint32_t* r, uint32_t addr) {
    asm volatile("ldmatrix.sync.aligned.m8n8.x4.shared.b16 {%0,%1,%2,%3}, [%4];"
                 : "=r"(r[0]), "=r"(r[1]), "=r"(r[2]), "=r"(r[3]) : "r"(addr));
}
__device__ __forceinline__ void mma_bf16(float* c, const uint32_t* a, uint32_t b0, uint32_t b1) {
    asm volatile("mma.sync.aligned.m16n8k16.row.col.f32.bf16.bf16.f32 "
                 "{%0,%1,%2,%3},{%4,%5,%6,%7},{%8,%9},{%0,%1,%2,%3};"
                 : "+f"(c[0]), "+f"(c[1]), "+f"(c[2]), "+f"(c[3])
                 : "r"(a[0]), "r"(a[1]), "r"(a[2]), "r"(a[3]), "r"(b0), "r"(b1));
}
__device__ __forceinline__ void mma_f16(float* c, const uint32_t* a, uint32_t b0, uint32_t b1) {
    asm volatile("mma.sync.aligned.m16n8k16.row.col.f32.f16.f16.f32 "
                 "{%0,%1,%2,%3},{%4,%5,%6,%7},{%8,%9},{%0,%1,%2,%3};"
                 : "+f"(c[0]), "+f"(c[1]), "+f"(c[2]), "+f"(c[3])
                 : "r"(a[0]), "r"(a[1]), "r"(a[2]), "r"(a[3]), "r"(b0), "r"(b1));
}
__device__ __forceinline__ float qredmax(float v) {
    v = fmaxf(v, __shfl_xor_sync(0xffffffffu, v, 1));
    v = fmaxf(v, __shfl_xor_sync(0xffffffffu, v, 2));
    return v;
}
__device__ __forceinline__ float qredsum(float v) {
    v += __shfl_xor_sync(0xffffffffu, v, 1);
    v += __shfl_xor_sync(0xffffffffu, v, 2);
    return v;
}

// ---------------- kernel 1: pooling + build M + channel sums ----------------
__global__ void pool_kernel(const float* __restrict__ x) {
    const int c = blockIdx.x, b = blockIdx.y;
    const float* xp = x + ((size_t)(b * CC + c)) * NN;
    __shared__ float xs[64][64];
    __shared__ float h3[64][64];
    __shared__ float h5[64][64];
    const int t = threadIdx.x;

    for (int p = t; p < NN; p += 128) xs[p >> 6][p & 63] = xp[p];
    __syncthreads();
    for (int p = t; p < NN; p += 128) {
        int h = p >> 6, w = p & 63;
        float c0 = xs[h][w];
        float l1 = (w > 0)  ? xs[h][w - 1] : 0.f;
        float r1 = (w < 63) ? xs[h][w + 1] : 0.f;
        float l2 = (w > 1)  ? xs[h][w - 2] : 0.f;
        float r2 = (w < 62) ? xs[h][w + 2] : 0.f;
        h3[h][w] = l1 + c0 + r1;
        h5[h][w] = l2 + l1 + c0 + r1 + r2;
    }
    __syncthreads();
    float s1 = 0.f, s3 = 0.f, s5 = 0.f;
    float* Mx = &d_M[b][c][0];
    float* M3 = &d_M[b][CC + c][0];
    float* M5 = &d_M[b][2 * CC + c][0];
    for (int p = t; p < NN; p += 128) {
        int h = p >> 6, w = p & 63;
        float v0 = xs[h][w];
        float u1 = (h > 0)  ? h3[h - 1][w] : 0.f;
        float dn1 = (h < 63) ? h3[h + 1][w] : 0.f;
        float u2 = (h > 1)  ? h5[h - 2][w] : 0.f;
        float dn2 = (h < 62) ? h5[h + 2][w] : 0.f;
        float u1b = (h > 0)  ? h5[h - 1][w] : 0.f;
        float dn1b = (h < 63) ? h5[h + 1][w] : 0.f;
        float p3 = (u1 + h3[h][w] + dn1) * (1.f / 9.f);
        float p5 = (u2 + u1b + h5[h][w] + dn1b + dn2) * (1.f / 25.f);
        Mx[p] = v0; M3[p] = p3; M5[p] = p5;
        s1 += v0; s3 += p3; s5 += p5;
    }
    __syncthreads();
    float* r1 = &xs[0][0];
    float* r3 = &h3[0][0];
    float* r5 = &h5[0][0];
    r1[t] = s1; r3[t] = s3; r5[t] = s5;
    __syncthreads();
    for (int off = 64; off > 0; off >>= 1) {
        if (t < off) { r1[t] += r1[t + off]; r3[t] += r3[t + off]; r5[t] += r5[t + off]; }
        __syncthreads();
    }
    if (t == 0) {
        d_S[0][b][c] = r1[0];
        d_S[1][b][c] = r3[0];
        d_S[2][b][c] = r5[0];
    }
}

// ---------------- kernel 2: tiny V computation ----------------
__global__ void vcalc_kernel(const float* __restrict__ W1, const float* __restrict__ W2) {
    __shared__ float m[BB][3];
    const int t = threadIdx.x;
    if (t < 6) {
        int k = t % 3, b = t / 3;
        float s = 0.f;
        for (int c = 0; c < CC; c++) { float v = d_S[k][b][c]; s += v * v; }
        m[b][k] = s * (1.f / ((float)NN * (float)NN));
    }
    __syncthreads();
    if (t < BB) {
        int b = t;
        float h[16];
        #pragma unroll
        for (int i = 0; i < 16; i++)
            h[i] = W1[i * 3 + 0] * m[b][0] + W1[i * 3 + 1] * m[b][1] + W1[i * 3 + 2] * m[b][2];
        float o[3];
        #pragma unroll
        for (int j = 0; j < 3; j++) {
            float s = 0.f;
            #pragma unroll
            for (int i = 0; i < 16; i++) s += W2[j * 16 + i] * h[i];
            o[j] = s;
        }
        float mx = fmaxf(o[0], fmaxf(o[1], o[2]));
        float e0 = expf(o[0] - mx), e1 = expf(o[1] - mx), e2 = expf(o[2] - mx);
        float inv = 1.f / (e0 + e1 + e2);
        d_sqrtV[b][0] = sqrtf(e0 * inv);
        d_sqrtV[b][1] = sqrtf(e1 * inv);
        d_sqrtV[b][2] = sqrtf(e2 * inv);
    }
}

// ---------------- kernel 2b: transpose + scale + bf16 convert ----------------
__global__ void split_kernel() {
    const int b = blockIdx.y;
    const int dtile = blockIdx.x % NCH;
    const int ntile = blockIdx.x / NCH;
    const int d0 = dtile * 64, n0 = ntile * 64;
    const float s = d_sqrtV[b][dtile >> 2];
    __shared__ float sme[64][65];
    const int t = threadIdx.x;
    #pragma unroll
    for (int it = 0; it < 4; it++) {
        int e = it * 256 + t;
        int r = e >> 4, c4 = (e & 15) << 2;
        float4 v = *(const float4*)&d_M[b][d0 + r][n0 + c4];
        sme[r][c4] = v.x; sme[r][c4 + 1] = v.y; sme[r][c4 + 2] = v.z; sme[r][c4 + 3] = v.w;
    }
    __syncthreads();
    #pragma unroll
    for (int it = 0; it < 2; it++) {
        int e = it * 256 + t;
        int r2 = e >> 3, g = e & 7;
        __nv_bfloat16 hv[8];
        #pragma unroll
        for (int q = 0; q < 8; q++)
            hv[q] = __float2bfloat16(sme[g * 8 + q][r2] * s);
        *(uint4*)&d_Mt[b][n0 + r2][d0 + g * 8] = *(uint4*)hv;
    }
}

// ---------------- kernel 3: g_x^T = (Wg @ x) as [b][i][n], fp16 ----------------
__global__ void gx_kernel(const float* __restrict__ x, const float* __restrict__ Wg) {
    const int b = blockIdx.y;
    const int n0 = blockIdx.x * 128;
    __shared__ float xs[32][128];
    __shared__ float Wgs[32][32];
    const int t = threadIdx.x;
    const int i = t & 31, ng = t >> 5;
    float acc[16];
    #pragma unroll
    for (int j = 0; j < 16; j++) acc[j] = 0.f;
    const float* xb = x + (size_t)b * CC * NN;
    for (int c0 = 0; c0 < CC; c0 += 32) {
        for (int e = t; e < 32 * 128; e += 256)
            xs[e >> 7][e & 127] = xb[(size_t)(c0 + (e >> 7)) * NN + n0 + (e & 127)];
        for (int e = t; e < 1024; e += 256) {
            int cc = e & 31, ii = e >> 5;
            Wgs[cc][ii] = Wg[ii * CC + c0 + cc];
        }
        __syncthreads();
        #pragma unroll 8
        for (int cc = 0; cc < 32; cc++) {
            float w = Wgs[cc][i];
            #pragma unroll
            for (int j = 0; j < 16; j++) acc[j] += w * xs[cc][ng * 16 + j];
        }
        __syncthreads();
    }
    __half hv[16];
    #pragma unroll
    for (int j = 0; j < 16; j++) hv[j] = __float2half(acc[j]);
    // 16 consecutive n per thread -> 2x uint4 stores
    *(uint4*)&d_GXT[b][i][n0 + ng * 16]     = *(uint4*)hv;
    *(uint4*)&d_GXT[b][i][n0 + ng * 16 + 8] = *(uint4*)(hv + 8);
}

// ---------------- kernel 4: mma.sync flash attention + Ww conv + residual ----------------
// grid (64, 2), 256 threads (8 warps). warp: wr=warp>>1 rows wr*16..+15; wc=warp&1 cols wc*128..+127.
__global__ __launch_bounds__(256, 1) void flash4_kernel(const float* __restrict__ x,
                                                        const float* __restrict__ Ww,
                                                        float* __restrict__ out) {
    extern __shared__ __align__(16) char sm[];
    float* smf = (float*)sm;
    const uint32_t sb = smem_u32(sm);
    const int tid = threadIdx.x, warp = tid >> 5, lane = tid & 31;
    const int b = blockIdx.y, i0 = blockIdx.x * TMQ;
    const int wr = warp >> 1, wc = warp & 1;

    float* pm  = smf + PM_OFF / 4;     // [2][64] partial max
    float* psm = smf + PSUM_OFF / 4;   // [2][64] partial sum
    float* mr  = smf + MR_OFF / 4;     // running max
    float* lr  = smf + LR_OFF / 4;     // running sum
    float* scr = smf + SCR_OFF / 4;    // rescale factor

    if (tid < 64) { mr[tid] = -3.0e38f; lr[tid] = 0.f; }
    const int r0 = wr * 16 + (lane >> 2);
    const int r1 = r0 + 8;
    const int nl = (lane & 7) | ((lane & 16) >> 1);  // ldmatrix B row-local
    const int kh = (lane >> 3) & 1;

    float yacc[8];
    #pragma unroll
    for (int a = 0; a < 8; a++) yacc[a] = 0.f;

    const __nv_bfloat16* Mb = &d_Mt[b][0][0];
    __syncthreads();

    for (int jt = 0; jt < NJT; jt++) {
        const int j0 = jt * TNK;

        // prologue: chunk 0 (stage 0) + VT tile, one commit group
        {
            uint32_t qb = sb;
            #pragma unroll
            for (int it = 0; it < 2; it++) {
                int e = it * 256 + tid, r = e >> 3, g = e & 7;
                cpa16(qb + sw128(r * 128 + g * 16), Mb + (size_t)(i0 + r) * DD + g * 8);
            }
            #pragma unroll
            for (int it = 0; it < 8; it++) {
                int e = it * 256 + tid, r = e >> 3, g = e & 7;
                cpa16(qb + KOFF + sw128(r * 128 + g * 16), Mb + (size_t)(j0 + r) * DD + g * 8);
            }
            #pragma unroll
            for (int it = 0; it < 4; it++) {
                int e = it * 256 + tid, r = e >> 5, g = e & 31;
                cpa16(sb + VTS_OFF + r * VT_PITCH + g * 16, &d_GXT[b][r][j0 + g * 8]);
            }
            cp_commit();
        }

        float acc[16][4];
        #pragma unroll
        for (int t = 0; t < 16; t++)
            #pragma unroll
            for (int q = 0; q < 4; q++) acc[t][q] = 0.f;

        for (int c = 0; c < NCH; c++) {
            if (c + 1 < NCH) {
                uint32_t qb = sb + ((c + 1) & 1) * STAGE_BYTES;
                const int d0 = (c + 1) * KC;
                #pragma unroll
                for (int it = 0; it < 2; it++) {
                    int e = it * 256 + tid, r = e >> 3, g = e & 7;
                    cpa16(qb + sw128(r * 128 + g * 16), Mb + (size_t)(i0 + r) * DD + d0 + g * 8);
                }
                #pragma unroll
                for (int it = 0; it < 8; it++) {
                    int e = it * 256 + tid, r = e >> 3, g = e & 7;
                    cpa16(qb + KOFF + sw128(r * 128 + g * 16), Mb + (size_t)(j0 + r) * DD + d0 + g * 8);
                }
                cp_commit();
                cp_wait1();
            } else {
                cp_wait0();
            }
            __syncthreads();
            const uint32_t qb = sb + (c & 1) * STAGE_BYTES;
            const uint32_t kb = qb + KOFF;
            #pragma unroll
            for (int k16 = 0; k16 < 4; k16++) {
                uint32_t afr[4];
                ldsm4(afr, qb + sw128((wr * 16 + (lane & 15)) * 128 + k16 * 32 + (lane >> 4) * 16));
                #pragma unroll
                for (int nt = 0; nt < 8; nt++) {
                    uint32_t bfr[4];
                    ldsm4(bfr, kb + sw128((wc * 128 + nt * 16 + nl) * 128 + k16 * 32 + kh * 16));
                    mma_bf16(acc[2 * nt],     afr, bfr[0], bfr[1]);
                    mma_bf16(acc[2 * nt + 1], afr, bfr[2], bfr[3]);
                }
            }
            __syncthreads();   // readers done before this stage is overwritten
        }

        // ---- online softmax ----
        float mx0 = -3.0e38f, mx1 = -3.0e38f;
        #pragma unroll
        for (int t = 0; t < 16; t++) {
            mx0 = fmaxf(mx0, fmaxf(acc[t][0], acc[t][1]));
            mx1 = fmaxf(mx1, fmaxf(acc[t][2], acc[t][3]));
        }
        mx0 = qredmax(mx0); mx1 = qredmax(mx1);
        if ((lane & 3) == 0) { pm[wc * 64 + r0] = mx0; pm[wc * 64 + r1] = mx1; }
        __syncthreads();
        if (tid < 64) {
            float mo = mr[tid];
            float mn = fmaxf(mo, fmaxf(pm[tid], pm[64 + tid]));
            scr[tid] = __expf(mo - mn);
            mr[tid] = mn;
        }
        __syncthreads();
        {
            float mn0 = mr[r0], mn1 = mr[r1];
            float s0 = 0.f, s1 = 0.f;
            #pragma unroll
            for (int t = 0; t < 16; t++) {
                float e0 = __expf(acc[t][0] - mn0);
                float e1 = __expf(acc[t][1] - mn0);
                float e2 = __expf(acc[t][2] - mn1);
                float e3 = __expf(acc[t][3] - mn1);
                s0 += e0 + e1; s1 += e2 + e3;
                int col = wc * 128 + t * 8 + (lane & 3) * 2;
                *(__half2*)(sm + PS_OFF + r0 * PS_PITCH + col * 2) = __floats2half2_rn(e0, e1);
                *(__half2*)(sm + PS_OFF + r1 * PS_PITCH + col * 2) = __floats2half2_rn(e2, e3);
            }
            s0 = qredsum(s0); s1 = qredsum(s1);
            if ((lane & 3) == 0) { psm[wc * 64 + r0] = s0; psm[wc * 64 + r1] = s1; }
            float sc0 = scr[r0], sc1 = scr[r1];
            yacc[0] *= sc0; yacc[1] *= sc0; yacc[2] *= sc1; yacc[3] *= sc1;
            yacc[4] *= sc0; yacc[5] *= sc0; yacc[6] *= sc1; yacc[7] *= sc1;
        }
        __syncthreads();
        if (tid < 64) lr[tid] = lr[tid] * scr[tid] + psm[tid] + psm[64 + tid];

        // ---- PV via fp16 mma: y[64][32] += P[64][256] @ VT^T ----
        #pragma unroll
        for (int k16 = 0; k16 < 16; k16++) {
            uint32_t afr[4], bfr[4];
            ldsm4(afr, sb + PS_OFF + (wr * 16 + (lane & 15)) * PS_PITCH + k16 * 32 + (lane >> 4) * 16);
            ldsm4(bfr, sb + VTS_OFF + (wc * 16 + nl) * VT_PITCH + k16 * 32 + kh * 16);
            mma_f16(yacc + 0, afr, bfr[0], bfr[1]);
            mma_f16(yacc + 4, afr, bfr[2], bfr[3]);
        }
        __syncthreads();   // P/VT reads done before next j-tile overwrites
    }

    // ---- epilogue ----
    float invl0 = 1.f / lr[r0], invl1 = 1.f / lr[r1];
    float (*ysT)[68] = (float (*)[68])(sm + YST_OFF);
    #pragma unroll
    for (int n = 0; n < 2; n++) {
        int c0 = wc * 16 + n * 8 + (lane & 3) * 2;
        ysT[c0][r0]     = yacc[n * 4 + 0] * invl0;
        ysT[c0 + 1][r0] = yacc[n * 4 + 1] * invl0;
        ysT[c0][r1]     = yacc[n * 4 + 2] * invl1;
        ysT[c0 + 1][r1] = yacc[n * 4 + 3] * invl1;
    }
    float* Ws = smf + WS_OFF / 4;  // [256][32]
    #pragma unroll
    for (int it = 0; it < 32; it++) Ws[it * 256 + tid] = Ww[it * 256 + tid];
    __syncthreads();

    const int r = tid & 63;
    const int cg = tid >> 6;
    float yreg[IN];
    #pragma unroll
    for (int i = 0; i < IN; i++) yreg[i] = ysT[i][r];
    const float* xb = x + (size_t)b * CC * NN;
    float* ob = out + (size_t)b * CC * NN;
    #pragma unroll 4
    for (int k = 0; k < 64; k++) {
        int c = cg * 64 + k;
        float s = 0.f;
        #pragma unroll
        for (int q = 0; q < 8; q++) {
            float4 w4 = *(const float4*)&Ws[c * 32 + q * 4];
            s += w4.x * yreg[q * 4] + w4.y * yreg[q * 4 + 1] + w4.z * yreg[q * 4 + 2] + w4.w * yreg[q * 4 + 3];
        }
        ob[(size_t)c * NN + i0 + r] = s + xb[(size_t)c * NN + i0 + r];
    }
}

extern "C" void kernel_launch(void* const* d_in, const int* in_sizes, int n_in,
                              void* d_out, int out_size) {
    const float* x  = (const float*)d_in[0];
    const float* Wg = (const float*)d_in[1];
    const float* Ww = (const float*)d_in[2];
    const float* W1 = (const float*)d_in[3];
    const float* W2 = (const float*)d_in[4];
    float* out = (float*)d_out;

    static int configured = 0;
    if (!configured) {
        cudaFuncSetAttribute(flash4_kernel, cudaFuncAttributeMaxDynamicSharedMemorySize, FLASH_SMEM);
        configured = 1;
    }

    pool_kernel<<<dim3(CC, BB), 128>>>(x);
    vcalc_kernel<<<1, 64>>>(W1, W2);
    split_kernel<<<dim3(NCH * (NN / 64), BB), 256>>>();
    gx_kernel<<<dim3(NN / 128, BB), 256>>>(x, Wg);
    flash4_kernel<<<dim3(NN / TMQ, BB), 256, FLASH_SMEM>>>(x, Ww, out);
}

// round 5
// speedup vs baseline: 8.9830x; 1.0543x over previous
#include <cuda_runtime.h>
#include <cuda_bf16.h>
#include <cuda_fp16.h>
#include <cstdint>

// Problem constants
#define BB 2
#define CC 256
#define NN 4096          // 64*64
#define DD 768           // 3*CC
#define IN 32            // inter

// Flash tiling
#define TMQ 64           // q rows per block
#define TNK 256          // keys per j-tile
#define KC 64            // feature chunk (=128B bf16 row)
#define NCH (DD / KC)    // 12
#define NJT (NN / TNK)   // 16

// SMEM layout (bytes)
#define STAGE_BYTES 40960      // Q tile 8192 + K tile 32768
#define KOFF 8192
#define PS_OFF  81920          // fp16 P [64][272]  (pitch 544B)
#define PS_PITCH 544
#define VTS_OFF 116736         // fp16 VT [32][272] (pitch 544B)
#define VT_PITCH 544
#define PM_OFF  134144         // fp32 [2][64]
#define PSUM_OFF 134656        // fp32 [2][64]
#define MR_OFF  135168         // fp32 [64]
#define LR_OFF  135424         // fp32 [64]
#define SCR_OFF 135680         // fp32 [64]
#define FLASH_SMEM 135936
#define YST_OFF PS_OFF         // epilogue fp32 [32][68] aliases PS
#define WS_OFF  0              // epilogue fp32 [256][32] aliases stage0

// Scratch (static device globals; no allocation)
__device__ float d_M[BB][DD][NN];                         // feature-major fp32 (pool output)
__device__ __align__(16) __nv_bfloat16 d_Mt[BB][NN][DD];  // token-major, scaled, bf16
__device__ __align__(16) __half d_GXT[BB][IN][NN];        // g_x as [b][i][n], fp16
__device__ float d_S[3][BB][CC];
__device__ float d_sqrtV[BB][3];

// ---------------- helpers ----------------
__device__ __forceinline__ uint32_t smem_u32(const void* p) {
    uint32_t a;
    asm("{ .reg .u64 t; cvta.to.shared.u64 t, %1; cvt.u32.u64 %0, t; }" : "=r"(a) : "l"(p));
    return a;
}
__device__ __forceinline__ uint32_t sw128(uint32_t bo) { return bo ^ ((bo >> 3) & 0x70); }

__device__ __forceinline__ void cpa16(uint32_t dst, const void* src) {
    asm volatile("cp.async.cg.shared.global [%0], [%1], 16;" :: "r"(dst), "l"(src));
}
__device__ __forceinline__ void cp_commit() { asm volatile("cp.async.commit_group;"); }
__device__ __forceinline__ void cp_wait0() { asm volatile("cp.async.wait_group 0;"); }

__device__ __forceinline__ void ldsm4(uint32_t* r, uint32_t addr) {
    asm volatile("ldmatrix.sync.aligned.m8n8.x4.shared.b16 {%0,%1,%2,%3}, [%4];"
                 : "=r"(r[0]), "=r"(r[1]), "=r"(r[2]), "=r"(r[3]) : "r"(addr));
}
__device__ __forceinline__ void mma_bf16(float* c, const uint32_t* a, uint32_t b0, uint32_t b1) {
    asm volatile("mma.sync.aligned.m16n8k16.row.col.f32.bf16.bf16.f32 "
                 "{%0,%1,%2,%3},{%4,%5,%6,%7},{%8,%9},{%0,%1,%2,%3};"
                 : "+f"(c[0]), "+f"(c[1]), "+f"(c[2]), "+f"(c[3])
                 : "r"(a[0]), "r"(a[1]), "r"(a[2]), "r"(a[3]), "r"(b0), "r"(b1));
}
__device__ __forceinline__ void mma_f16(float* c, const uint32_t* a, uint32_t b0, uint32_t b1) {
    asm volatile("mma.sync.aligned.m16n8k16.row.col.f32.f16.f16.f32 "
                 "{%0,%1,%2,%3},{%4,%5,%6,%7},{%8,%9},{%0,%1,%2,%3};"
                 : "+f"(c[0]), "+f"(c[1]), "+f"(c[2]), "+f"(c[3])
                 : "r"(a[0]), "r"(a[1]), "r"(a[2]), "r"(a[3]), "r"(b0), "r"(b1));
}
__device__ __forceinline__ float qredmax(float v) {
    v = fmaxf(v, __shfl_xor_sync(0xffffffffu, v, 1));
    v = fmaxf(v, __shfl_xor_sync(0xffffffffu, v, 2));
    return v;
}
__device__ __forceinline__ float qredsum(float v) {
    v += __shfl_xor_sync(0xffffffffu, v, 1);
    v += __shfl_xor_sync(0xffffffffu, v, 2);
    return v;
}

// ---------------- kernel 1: pooling + build M + channel sums ----------------
// grid (256, 2), block 256. One (b,c) plane per block.
__global__ void pool_kernel(const float* __restrict__ x) {
    const int c = blockIdx.x, b = blockIdx.y;
    const float* xp = x + ((size_t)(b * CC + c)) * NN;
    __shared__ float xs[64][64];
    __shared__ float h3[64][64];
    __shared__ float h5[64][64];
    const int t = threadIdx.x;

    for (int p = t; p < NN; p += 256) xs[p >> 6][p & 63] = xp[p];
    __syncthreads();
    for (int p = t; p < NN; p += 256) {
        int h = p >> 6, w = p & 63;
        float c0 = xs[h][w];
        float l1 = (w > 0)  ? xs[h][w - 1] : 0.f;
        float r1 = (w < 63) ? xs[h][w + 1] : 0.f;
        float l2 = (w > 1)  ? xs[h][w - 2] : 0.f;
        float r2 = (w < 62) ? xs[h][w + 2] : 0.f;
        h3[h][w] = l1 + c0 + r1;
        h5[h][w] = l2 + l1 + c0 + r1 + r2;
    }
    __syncthreads();
    float s1 = 0.f, s3 = 0.f, s5 = 0.f;
    float* Mx = &d_M[b][c][0];
    float* M3 = &d_M[b][CC + c][0];
    float* M5 = &d_M[b][2 * CC + c][0];
    for (int p = t; p < NN; p += 256) {
        int h = p >> 6, w = p & 63;
        float v0 = xs[h][w];
        float u1 = (h > 0)  ? h3[h - 1][w] : 0.f;
        float dn1 = (h < 63) ? h3[h + 1][w] : 0.f;
        float u2 = (h > 1)  ? h5[h - 2][w] : 0.f;
        float dn2 = (h < 62) ? h5[h + 2][w] : 0.f;
        float u1b = (h > 0)  ? h5[h - 1][w] : 0.f;
        float dn1b = (h < 63) ? h5[h + 1][w] : 0.f;
        float p3 = (u1 + h3[h][w] + dn1) * (1.f / 9.f);
        float p5 = (u2 + u1b + h5[h][w] + dn1b + dn2) * (1.f / 25.f);
        Mx[p] = v0; M3[p] = p3; M5[p] = p5;
        s1 += v0; s3 += p3; s5 += p5;
    }
    __syncthreads();
    float* r1 = &xs[0][0];
    float* r3 = &h3[0][0];
    float* r5 = &h5[0][0];
    r1[t] = s1; r3[t] = s3; r5[t] = s5;
    __syncthreads();
    for (int off = 128; off > 0; off >>= 1) {
        if (t < off) { r1[t] += r1[t + off]; r3[t] += r3[t + off]; r5[t] += r5[t + off]; }
        __syncthreads();
    }
    if (t == 0) {
        d_S[0][b][c] = r1[0];
        d_S[1][b][c] = r3[0];
        d_S[2][b][c] = r5[0];
    }
}

// ---------------- kernel 2: tiny V computation ----------------
__global__ void vcalc_kernel(const float* __restrict__ W1, const float* __restrict__ W2) {
    __shared__ float m[BB][3];
    const int t = threadIdx.x;
    if (t < 6) {
        int k = t % 3, b = t / 3;
        float s = 0.f;
        for (int c = 0; c < CC; c++) { float v = d_S[k][b][c]; s += v * v; }
        m[b][k] = s * (1.f / ((float)NN * (float)NN));
    }
    __syncthreads();
    if (t < BB) {
        int b = t;
        float h[16];
        #pragma unroll
        for (int i = 0; i < 16; i++)
            h[i] = W1[i * 3 + 0] * m[b][0] + W1[i * 3 + 1] * m[b][1] + W1[i * 3 + 2] * m[b][2];
        float o[3];
        #pragma unroll
        for (int j = 0; j < 3; j++) {
            float s = 0.f;
            #pragma unroll
            for (int i = 0; i < 16; i++) s += W2[j * 16 + i] * h[i];
            o[j] = s;
        }
        float mx = fmaxf(o[0], fmaxf(o[1], o[2]));
        float e0 = expf(o[0] - mx), e1 = expf(o[1] - mx), e2 = expf(o[2] - mx);
        float inv = 1.f / (e0 + e1 + e2);
        d_sqrtV[b][0] = sqrtf(e0 * inv);
        d_sqrtV[b][1] = sqrtf(e1 * inv);
        d_sqrtV[b][2] = sqrtf(e2 * inv);
    }
}

// ---------------- kernel 2b: transpose + scale + bf16 convert ----------------
__global__ void split_kernel() {
    const int b = blockIdx.y;
    const int dtile = blockIdx.x % NCH;
    const int ntile = blockIdx.x / NCH;
    const int d0 = dtile * 64, n0 = ntile * 64;
    const float s = d_sqrtV[b][dtile >> 2];
    __shared__ float sme[64][65];
    const int t = threadIdx.x;
    #pragma unroll
    for (int it = 0; it < 4; it++) {
        int e = it * 256 + t;
        int r = e >> 4, c4 = (e & 15) << 2;
        float4 v = *(const float4*)&d_M[b][d0 + r][n0 + c4];
        sme[r][c4] = v.x; sme[r][c4 + 1] = v.y; sme[r][c4 + 2] = v.z; sme[r][c4 + 3] = v.w;
    }
    __syncthreads();
    #pragma unroll
    for (int it = 0; it < 2; it++) {
        int e = it * 256 + t;
        int r2 = e >> 3, g = e & 7;
        __nv_bfloat16 hv[8];
        #pragma unroll
        for (int q = 0; q < 8; q++)
            hv[q] = __float2bfloat16(sme[g * 8 + q][r2] * s);
        *(uint4*)&d_Mt[b][n0 + r2][d0 + g * 8] = *(uint4*)hv;
    }
}

// ---------------- kernel 3: g_x^T = (Wg @ x) as [b][i][n], fp16 ----------------
// grid (NN/32 = 128, 2), block 256. Block: 32 n's, all 256 c, 64-c chunks.
__global__ void gx_kernel(const float* __restrict__ x, const float* __restrict__ Wg) {
    const int b = blockIdx.y;
    const int n0 = blockIdx.x * 32;
    __shared__ float xs[64 * 32];
    __shared__ float Wgs[64][33];
    const int t = threadIdx.x;
    const int i = t & 31, ng = t >> 5;   // ng 0..7 -> 4 n's each
    float acc[4] = {0.f, 0.f, 0.f, 0.f};
    const float* xb = x + (size_t)b * CC * NN;
    for (int c0 = 0; c0 < CC; c0 += 64) {
        #pragma unroll
        for (int it = 0; it < 2; it++) {
            int e = it * 256 + t;
            int r = e >> 3, q = e & 7;
            *(float4*)&xs[r * 32 + q * 4] = *(const float4*)&xb[(size_t)(c0 + r) * NN + n0 + q * 4];
        }
        #pragma unroll
        for (int it = 0; it < 8; it++) {
            int e = it * 256 + t;
            int ii = e >> 6, cc = e & 63;
            Wgs[cc][ii] = Wg[ii * CC + c0 + cc];
        }
        __syncthreads();
        #pragma unroll 16
        for (int cc = 0; cc < 64; cc++) {
            float w = Wgs[cc][i];
            float4 xv = *(const float4*)&xs[cc * 32 + ng * 4];
            acc[0] += w * xv.x; acc[1] += w * xv.y; acc[2] += w * xv.z; acc[3] += w * xv.w;
        }
        __syncthreads();
    }
    __half hv[4];
    #pragma unroll
    for (int j = 0; j < 4; j++) hv[j] = __float2half(acc[j]);
    *(uint2*)&d_GXT[b][i][n0 + ng * 4] = *(uint2*)hv;
}

// ---------------- kernel 4: mma.sync flash attention + Ww conv + residual ----------------
// grid (64, 2), 256 threads (8 warps). warp: wr=warp>>1 rows wr*16..+15; wc=warp&1 cols wc*128..+127.
__global__ __launch_bounds__(256, 1) void flash4_kernel(const float* __restrict__ x,
                                                        const float* __restrict__ Ww,
                                                        float* __restrict__ out) {
    extern __shared__ __align__(16) char sm[];
    float* smf = (float*)sm;
    const uint32_t sb = smem_u32(sm);
    const int tid = threadIdx.x, warp = tid >> 5, lane = tid & 31;
    const int b = blockIdx.y, i0 = blockIdx.x * TMQ;
    const int wr = warp >> 1, wc = warp & 1;

    float* pm  = smf + PM_OFF / 4;     // [2][64] partial max
    float* psm = smf + PSUM_OFF / 4;   // [2][64] partial sum
    float* mr  = smf + MR_OFF / 4;     // running max
    float* lr  = smf + LR_OFF / 4;     // running sum
    float* scr = smf + SCR_OFF / 4;    // rescale factor

    if (tid < 64) { mr[tid] = -3.0e38f; lr[tid] = 0.f; }
    const int r0 = wr * 16 + (lane >> 2);
    const int r1 = r0 + 8;
    const int nl = (lane & 7) | ((lane & 16) >> 1);  // ldmatrix B row-local
    const int kh = (lane >> 3) & 1;

    float yacc[8];
    #pragma unroll
    for (int a = 0; a < 8; a++) yacc[a] = 0.f;

    const __nv_bfloat16* Mb = &d_Mt[b][0][0];
    __syncthreads();

    for (int jt = 0; jt < NJT; jt++) {
        const int j0 = jt * TNK;

        // prologue: chunk 0 (stage 0) + VT tile, one commit group
        {
            uint32_t qb = sb;
            #pragma unroll
            for (int it = 0; it < 2; it++) {
                int e = it * 256 + tid, r = e >> 3, g = e & 7;
                cpa16(qb + sw128(r * 128 + g * 16), Mb + (size_t)(i0 + r) * DD + g * 8);
            }
            #pragma unroll
            for (int it = 0; it < 8; it++) {
                int e = it * 256 + tid, r = e >> 3, g = e & 7;
                cpa16(qb + KOFF + sw128(r * 128 + g * 16), Mb + (size_t)(j0 + r) * DD + g * 8);
            }
            #pragma unroll
            for (int it = 0; it < 4; it++) {
                int e = it * 256 + tid, r = e >> 5, g = e & 31;
                cpa16(sb + VTS_OFF + r * VT_PITCH + g * 16, &d_GXT[b][r][j0 + g * 8]);
            }
            cp_commit();
        }

        float acc[16][4];
        #pragma unroll
        for (int t = 0; t < 16; t++)
            #pragma unroll
            for (int q = 0; q < 4; q++) acc[t][q] = 0.f;

        for (int c = 0; c < NCH; c++) {
            // wait for buf[c] data (the only outstanding group), then one barrier
            cp_wait0();
            __syncthreads();
            // prefetch buf[c+1] (overwrites buf[c-1]; barrier above makes that safe)
            if (c + 1 < NCH) {
                uint32_t qb = sb + ((c + 1) & 1) * STAGE_BYTES;
                const int d0 = (c + 1) * KC;
                #pragma unroll
                for (int it = 0; it < 2; it++) {
                    int e = it * 256 + tid, r = e >> 3, g = e & 7;
                    cpa16(qb + sw128(r * 128 + g * 16), Mb + (size_t)(i0 + r) * DD + d0 + g * 8);
                }
                #pragma unroll
                for (int it = 0; it < 8; it++) {
                    int e = it * 256 + tid, r = e >> 3, g = e & 7;
                    cpa16(qb + KOFF + sw128(r * 128 + g * 16), Mb + (size_t)(j0 + r) * DD + d0 + g * 8);
                }
                cp_commit();
            }
            const uint32_t qb = sb + (c & 1) * STAGE_BYTES;
            const uint32_t kb = qb + KOFF;
            #pragma unroll
            for (int k16 = 0; k16 < 4; k16++) {
                uint32_t afr[4];
                ldsm4(afr, qb + sw128((wr * 16 + (lane & 15)) * 128 + k16 * 32 + (lane >> 4) * 16));
                #pragma unroll
                for (int nt = 0; nt < 8; nt++) {
                    uint32_t bfr[4];
                    ldsm4(bfr, kb + sw128((wc * 128 + nt * 16 + nl) * 128 + k16 * 32 + kh * 16));
                    mma_bf16(acc[2 * nt],     afr, bfr[0], bfr[1]);
                    mma_bf16(acc[2 * nt + 1], afr, bfr[2], bfr[3]);
                }
            }
        }

        // ---- online softmax ----
        float mx0 = -3.0e38f, mx1 = -3.0e38f;
        #pragma unroll
        for (int t = 0; t < 16; t++) {
            mx0 = fmaxf(mx0, fmaxf(acc[t][0], acc[t][1]));
            mx1 = fmaxf(mx1, fmaxf(acc[t][2], acc[t][3]));
        }
        mx0 = qredmax(mx0); mx1 = qredmax(mx1);
        if ((lane & 3) == 0) { pm[wc * 64 + r0] = mx0; pm[wc * 64 + r1] = mx1; }
        __syncthreads();
        if (tid < 64) {
            float mo = mr[tid];
            float mn = fmaxf(mo, fmaxf(pm[tid], pm[64 + tid]));
            scr[tid] = __expf(mo - mn);
            mr[tid] = mn;
        }
        __syncthreads();
        {
            float mn0 = mr[r0], mn1 = mr[r1];
            float s0 = 0.f, s1 = 0.f;
            #pragma unroll
            for (int t = 0; t < 16; t++) {
                float e0 = __expf(acc[t][0] - mn0);
                float e1 = __expf(acc[t][1] - mn0);
                float e2 = __expf(acc[t][2] - mn1);
                float e3 = __expf(acc[t][3] - mn1);
                s0 += e0 + e1; s1 += e2 + e3;
                int col = wc * 128 + t * 8 + (lane & 3) * 2;
                *(__half2*)(sm + PS_OFF + r0 * PS_PITCH + col * 2) = __floats2half2_rn(e0, e1);
                *(__half2*)(sm + PS_OFF + r1 * PS_PITCH + col * 2) = __floats2half2_rn(e2, e3);
            }
            s0 = qredsum(s0); s1 = qredsum(s1);
            if ((lane & 3) == 0) { psm[wc * 64 + r0] = s0; psm[wc * 64 + r1] = s1; }
            float sc0 = scr[r0], sc1 = scr[r1];
            yacc[0] *= sc0; yacc[1] *= sc0; yacc[2] *= sc1; yacc[3] *= sc1;
            yacc[4] *= sc0; yacc[5] *= sc0; yacc[6] *= sc1; yacc[7] *= sc1;
        }
        __syncthreads();
        if (tid < 64) lr[tid] = lr[tid] * scr[tid] + psm[tid] + psm[64 + tid];

        // ---- PV via fp16 mma: y[64][32] += P[64][256] @ VT^T ----
        #pragma unroll
        for (int k16 = 0; k16 < 16; k16++) {
            uint32_t afr[4], bfr[4];
            ldsm4(afr, sb + PS_OFF + (wr * 16 + (lane & 15)) * PS_PITCH + k16 * 32 + (lane >> 4) * 16);
            ldsm4(bfr, sb + VTS_OFF + (wc * 16 + nl) * VT_PITCH + k16 * 32 + kh * 16);
            mma_f16(yacc + 0, afr, bfr[0], bfr[1]);
            mma_f16(yacc + 4, afr, bfr[2], bfr[3]);
        }
        __syncthreads();   // P/VT reads done before next j-tile overwrites
    }

    // ---- epilogue ----
    float invl0 = 1.f / lr[r0], invl1 = 1.f / lr[r1];
    float (*ysT)[68] = (float (*)[68])(sm + YST_OFF);
    #pragma unroll
    for (int n = 0; n < 2; n++) {
        int c0 = wc * 16 + n * 8 + (lane & 3) * 2;
        ysT[c0][r0]     = yacc[n * 4 + 0] * invl0;
        ysT[c0 + 1][r0] = yacc[n * 4 + 1] * invl0;
        ysT[c0][r1]     = yacc[n * 4 + 2] * invl1;
        ysT[c0 + 1][r1] = yacc[n * 4 + 3] * invl1;
    }
    float* Ws = smf + WS_OFF / 4;  // [256][32]
    #pragma unroll
    for (int it = 0; it < 32; it++) Ws[it * 256 + tid] = Ww[it * 256 + tid];
    __syncthreads();

    const int r = tid & 63;
    const int cg = tid >> 6;
    float yreg[IN];
    #pragma unroll
    for (int i = 0; i < IN; i++) yreg[i] = ysT[i][r];
    const float* xb = x + (size_t)b * CC * NN;
    float* ob = out + (size_t)b * CC * NN;
    #pragma unroll 4
    for (int k = 0; k < 64; k++) {
        int c = cg * 64 + k;
        float s = 0.f;
        #pragma unroll
        for (int q = 0; q < 8; q++) {
            float4 w4 = *(const float4*)&Ws[c * 32 + q * 4];
            s += w4.x * yreg[q * 4] + w4.y * yreg[q * 4 + 1] + w4.z * yreg[q * 4 + 2] + w4.w * yreg[q * 4 + 3];
        }
        ob[(size_t)c * NN + i0 + r] = s + xb[(size_t)c * NN + i0 + r];
    }
}

extern "C" void kernel_launch(void* const* d_in, const int* in_sizes, int n_in,
                              void* d_out, int out_size) {
    const float* x  = (const float*)d_in[0];
    const float* Wg = (const float*)d_in[1];
    const float* Ww = (const float*)d_in[2];
    const float* W1 = (const float*)d_in[3];
    const float* W2 = (const float*)d_in[4];
    float* out = (float*)d_out;

    static int configured = 0;
    if (!configured) {
        cudaFuncSetAttribute(flash4_kernel, cudaFuncAttributeMaxDynamicSharedMemorySize, FLASH_SMEM);
        configured = 1;
    }

    pool_kernel<<<dim3(CC, BB), 256>>>(x);
    vcalc_kernel<<<1, 64>>>(W1, W2);
    split_kernel<<<dim3(NCH * (NN / 64), BB), 256>>>();
    gx_kernel<<<dim3(NN / 32, BB), 256>>>(x, Wg);
    flash4_kernel<<<dim3(NN / TMQ, BB), 256, FLASH_SMEM>>>(x, Ww, out);
}

// round 6
// speedup vs baseline: 12.0527x; 1.3417x over previous
#include <cuda_runtime.h>
#include <cuda_bf16.h>
#include <cuda_fp16.h>
#include <cstdint>

// Problem constants
#define BB 2
#define CC 256
#define NN 4096          // 64*64
#define DD 768           // 3*CC
#define IN 32            // inter

// Flash tiling
#define TMQ 128          // q rows per block
#define TNK 256          // keys per j-tile
#define KC 64            // feature chunk (=128B bf16 row)
#define NCH (DD / KC)    // 12
#define SPLITS 2
#define KEYS (NN / SPLITS)   // 2048
#define NJT (KEYS / TNK)     // 8

// SMEM layout (bytes) for flash
#define QBYTES 16384           // 128 x 64 bf16
#define KOFF   16384
#define STAGE_BYTES 49152      // Q 16K + K 32K
#define VTS_OFF 98304          // fp16 VT [32][272] (pitch 544B)
#define VT_PITCH 544
#define PM_OFF   115712        // fp32 [2][128]
#define PSUM_OFF 116736        // fp32 [2][128]
#define MR_OFF   117760        // fp32 [128]
#define LR_OFF   118272
#define SCR_OFF  118784
#define FLASH_SMEM 119296

// Scratch (static device globals; no allocation)
__device__ float d_M[BB][DD][NN];                         // feature-major fp32 (pool output)
__device__ __align__(16) __nv_bfloat16 d_Mt[BB][NN][DD];  // token-major, scaled, bf16
__device__ __align__(16) __half d_GXT[BB][IN][NN];        // g_x as [b][i][n], fp16
__device__ float d_S[3][BB][CC];
__device__ float d_sqrtV[BB][3];
__device__ float d_part[BB * SPLITS][NN][IN];             // split partial O (unnormalized)
__device__ float2 d_ml[BB * SPLITS][NN];                  // split (m, l)

// ---------------- helpers ----------------
__device__ __forceinline__ uint32_t smem_u32(const void* p) {
    uint32_t a;
    asm("{ .reg .u64 t; cvta.to.shared.u64 t, %1; cvt.u32.u64 %0, t; }" : "=r"(a) : "l"(p));
    return a;
}
__device__ __forceinline__ uint32_t sw128(uint32_t bo) { return bo ^ ((bo >> 3) & 0x70); }

__device__ __forceinline__ void cpa16(uint32_t dst, const void* src) {
    asm volatile("cp.async.cg.shared.global [%0], [%1], 16;" :: "r"(dst), "l"(src));
}
__device__ __forceinline__ void cp_commit() { asm volatile("cp.async.commit_group;"); }
__device__ __forceinline__ void cp_wait0() { asm volatile("cp.async.wait_group 0;"); }

__device__ __forceinline__ void ldsm4(uint32_t* r, uint32_t addr) {
    asm volatile("ldmatrix.sync.aligned.m8n8.x4.shared.b16 {%0,%1,%2,%3}, [%4];"
                 : "=r"(r[0]), "=r"(r[1]), "=r"(r[2]), "=r"(r[3]) : "r"(addr));
}
__device__ __forceinline__ void mma_bf16(float* c, const uint32_t* a, uint32_t b0, uint32_t b1) {
    asm volatile("mma.sync.aligned.m16n8k16.row.col.f32.bf16.bf16.f32 "
                 "{%0,%1,%2,%3},{%4,%5,%6,%7},{%8,%9},{%0,%1,%2,%3};"
                 : "+f"(c[0]), "+f"(c[1]), "+f"(c[2]), "+f"(c[3])
                 : "r"(a[0]), "r"(a[1]), "r"(a[2]), "r"(a[3]), "r"(b0), "r"(b1));
}
__device__ __forceinline__ void mma_f16(float* c, const uint32_t* a, uint32_t b0, uint32_t b1) {
    asm volatile("mma.sync.aligned.m16n8k16.row.col.f32.f16.f16.f32 "
                 "{%0,%1,%2,%3},{%4,%5,%6,%7},{%8,%9},{%0,%1,%2,%3};"
                 : "+f"(c[0]), "+f"(c[1]), "+f"(c[2]), "+f"(c[3])
                 : "r"(a[0]), "r"(a[1]), "r"(a[2]), "r"(a[3]), "r"(b0), "r"(b1));
}
__device__ __forceinline__ float qredmax(float v) {
    v = fmaxf(v, __shfl_xor_sync(0xffffffffu, v, 1));
    v = fmaxf(v, __shfl_xor_sync(0xffffffffu, v, 2));
    return v;
}
__device__ __forceinline__ float qredsum(float v) {
    v += __shfl_xor_sync(0xffffffffu, v, 1);
    v += __shfl_xor_sync(0xffffffffu, v, 2);
    return v;
}

// ---------------- kernel 1: pooling + build M + channel sums ----------------
__global__ void pool_kernel(const float* __restrict__ x) {
    const int c = blockIdx.x, b = blockIdx.y;
    const float* xp = x + ((size_t)(b * CC + c)) * NN;
    __shared__ float xs[64][64];
    __shared__ float h3[64][64];
    __shared__ float h5[64][64];
    const int t = threadIdx.x;

    for (int p = t; p < NN; p += 256) xs[p >> 6][p & 63] = xp[p];
    __syncthreads();
    for (int p = t; p < NN; p += 256) {
        int h = p >> 6, w = p & 63;
        float c0 = xs[h][w];
        float l1 = (w > 0)  ? xs[h][w - 1] : 0.f;
        float r1 = (w < 63) ? xs[h][w + 1] : 0.f;
        float l2 = (w > 1)  ? xs[h][w - 2] : 0.f;
        float r2 = (w < 62) ? xs[h][w + 2] : 0.f;
        h3[h][w] = l1 + c0 + r1;
        h5[h][w] = l2 + l1 + c0 + r1 + r2;
    }
    __syncthreads();
    float s1 = 0.f, s3 = 0.f, s5 = 0.f;
    float* Mx = &d_M[b][c][0];
    float* M3 = &d_M[b][CC + c][0];
    float* M5 = &d_M[b][2 * CC + c][0];
    for (int p = t; p < NN; p += 256) {
        int h = p >> 6, w = p & 63;
        float v0 = xs[h][w];
        float u1 = (h > 0)  ? h3[h - 1][w] : 0.f;
        float dn1 = (h < 63) ? h3[h + 1][w] : 0.f;
        float u2 = (h > 1)  ? h5[h - 2][w] : 0.f;
        float dn2 = (h < 62) ? h5[h + 2][w] : 0.f;
        float u1b = (h > 0)  ? h5[h - 1][w] : 0.f;
        float dn1b = (h < 63) ? h5[h + 1][w] : 0.f;
        float p3 = (u1 + h3[h][w] + dn1) * (1.f / 9.f);
        float p5 = (u2 + u1b + h5[h][w] + dn1b + dn2) * (1.f / 25.f);
        Mx[p] = v0; M3[p] = p3; M5[p] = p5;
        s1 += v0; s3 += p3; s5 += p5;
    }
    __syncthreads();
    float* r1 = &xs[0][0];
    float* r3 = &h3[0][0];
    float* r5 = &h5[0][0];
    r1[t] = s1; r3[t] = s3; r5[t] = s5;
    __syncthreads();
    for (int off = 128; off > 0; off >>= 1) {
        if (t < off) { r1[t] += r1[t + off]; r3[t] += r3[t + off]; r5[t] += r5[t + off]; }
        __syncthreads();
    }
    if (t == 0) {
        d_S[0][b][c] = r1[0];
        d_S[1][b][c] = r3[0];
        d_S[2][b][c] = r5[0];
    }
}

// ---------------- kernel 2: tiny V computation ----------------
__global__ void vcalc_kernel(const float* __restrict__ W1, const float* __restrict__ W2) {
    __shared__ float m[BB][3];
    const int t = threadIdx.x;
    if (t < 6) {
        int k = t % 3, b = t / 3;
        float s = 0.f;
        for (int c = 0; c < CC; c++) { float v = d_S[k][b][c]; s += v * v; }
        m[b][k] = s * (1.f / ((float)NN * (float)NN));
    }
    __syncthreads();
    if (t < BB) {
        int b = t;
        float h[16];
        #pragma unroll
        for (int i = 0; i < 16; i++)
            h[i] = W1[i * 3 + 0] * m[b][0] + W1[i * 3 + 1] * m[b][1] + W1[i * 3 + 2] * m[b][2];
        float o[3];
        #pragma unroll
        for (int j = 0; j < 3; j++) {
            float s = 0.f;
            #pragma unroll
            for (int i = 0; i < 16; i++) s += W2[j * 16 + i] * h[i];
            o[j] = s;
        }
        float mx = fmaxf(o[0], fmaxf(o[1], o[2]));
        float e0 = expf(o[0] - mx), e1 = expf(o[1] - mx), e2 = expf(o[2] - mx);
        float inv = 1.f / (e0 + e1 + e2);
        d_sqrtV[b][0] = sqrtf(e0 * inv);
        d_sqrtV[b][1] = sqrtf(e1 * inv);
        d_sqrtV[b][2] = sqrtf(e2 * inv);
    }
}

// ---------------- kernel 2b: transpose + scale + bf16 convert ----------------
__global__ void split_kernel() {
    const int b = blockIdx.y;
    const int dtile = blockIdx.x % NCH;
    const int ntile = blockIdx.x / NCH;
    const int d0 = dtile * 64, n0 = ntile * 64;
    const float s = d_sqrtV[b][dtile >> 2];
    __shared__ float sme[64][65];
    const int t = threadIdx.x;
    #pragma unroll
    for (int it = 0; it < 4; it++) {
        int e = it * 256 + t;
        int r = e >> 4, c4 = (e & 15) << 2;
        float4 v = *(const float4*)&d_M[b][d0 + r][n0 + c4];
        sme[r][c4] = v.x; sme[r][c4 + 1] = v.y; sme[r][c4 + 2] = v.z; sme[r][c4 + 3] = v.w;
    }
    __syncthreads();
    #pragma unroll
    for (int it = 0; it < 2; it++) {
        int e = it * 256 + t;
        int r2 = e >> 3, g = e & 7;
        __nv_bfloat16 hv[8];
        #pragma unroll
        for (int q = 0; q < 8; q++)
            hv[q] = __float2bfloat16(sme[g * 8 + q][r2] * s);
        *(uint4*)&d_Mt[b][n0 + r2][d0 + g * 8] = *(uint4*)hv;
    }
}

// ---------------- kernel 3: g_x^T = (Wg @ x) as [b][i][n], fp16 ----------------
__global__ void gx_kernel(const float* __restrict__ x, const float* __restrict__ Wg) {
    const int b = blockIdx.y;
    const int n0 = blockIdx.x * 32;
    __shared__ float xs[64 * 32];
    __shared__ float Wgs[64][33];
    const int t = threadIdx.x;
    const int i = t & 31, ng = t >> 5;
    float acc[4] = {0.f, 0.f, 0.f, 0.f};
    const float* xb = x + (size_t)b * CC * NN;
    for (int c0 = 0; c0 < CC; c0 += 64) {
        #pragma unroll
        for (int it = 0; it < 2; it++) {
            int e = it * 256 + t;
            int r = e >> 3, q = e & 7;
            *(float4*)&xs[r * 32 + q * 4] = *(const float4*)&xb[(size_t)(c0 + r) * NN + n0 + q * 4];
        }
        #pragma unroll
        for (int it = 0; it < 8; it++) {
            int e = it * 256 + t;
            int ii = e >> 6, cc = e & 63;
            Wgs[cc][ii] = Wg[ii * CC + c0 + cc];
        }
        __syncthreads();
        #pragma unroll 16
        for (int cc = 0; cc < 64; cc++) {
            float w = Wgs[cc][i];
            float4 xv = *(const float4*)&xs[cc * 32 + ng * 4];
            acc[0] += w * xv.x; acc[1] += w * xv.y; acc[2] += w * xv.z; acc[3] += w * xv.w;
        }
        __syncthreads();
    }
    __half hv[4];
    #pragma unroll
    for (int j = 0; j < 4; j++) hv[j] = __float2half(acc[j]);
    *(uint2*)&d_GXT[b][i][n0 + ng * 4] = *(uint2*)hv;
}

// ---------------- kernel 4: split-K mma.sync flash attention ----------------
// grid (NN/TMQ=32, SPLITS, BB), 256 threads (8 warps).
// warp: wr=warp>>1 rows wr*32..+31; wc=warp&1 cols wc*128..+127.
__global__ __launch_bounds__(256, 1) void flash5_kernel() {
    extern __shared__ __align__(16) char sm[];
    float* smf = (float*)sm;
    const uint32_t sb = smem_u32(sm);
    const int tid = threadIdx.x, warp = tid >> 5, lane = tid & 31;
    const int i0 = blockIdx.x * TMQ;
    const int split = blockIdx.y;
    const int b = blockIdx.z;
    const int wr = warp >> 1, wc = warp & 1;

    float* pm  = smf + PM_OFF / 4;     // [2][128]
    float* psm = smf + PSUM_OFF / 4;   // [2][128]
    float* mr  = smf + MR_OFF / 4;
    float* lr  = smf + LR_OFF / 4;
    float* scr = smf + SCR_OFF / 4;

    if (tid < TMQ) { mr[tid] = -3.0e38f; lr[tid] = 0.f; }
    __syncthreads();

    const int nl = (lane & 7) | ((lane & 16) >> 1);
    const int kh = (lane >> 3) & 1;
    const int ra = wr * 32 + (lane >> 2);   // rt0 row-a (global block row)

    float yacc[2][4][4];
    #pragma unroll
    for (int rt = 0; rt < 2; rt++)
        #pragma unroll
        for (int ng = 0; ng < 4; ng++)
            #pragma unroll
            for (int q = 0; q < 4; q++) yacc[rt][ng][q] = 0.f;

    const __nv_bfloat16* Mb = &d_Mt[b][0][0];

    for (int jt = 0; jt < NJT; jt++) {
        const int j0 = split * KEYS + jt * TNK;

        // prologue: chunk 0 (stage 0) + VT tile
        {
            uint32_t qb = sb;
            #pragma unroll
            for (int it = 0; it < 4; it++) {
                int e = it * 256 + tid, r = e >> 3, g = e & 7;
                cpa16(qb + sw128(r * 128 + g * 16), Mb + (size_t)(i0 + r) * DD + g * 8);
            }
            #pragma unroll
            for (int it = 0; it < 8; it++) {
                int e = it * 256 + tid, r = e >> 3, g = e & 7;
                cpa16(qb + KOFF + sw128(r * 128 + g * 16), Mb + (size_t)(j0 + r) * DD + g * 8);
            }
            #pragma unroll
            for (int it = 0; it < 4; it++) {
                int e = it * 256 + tid, r = e >> 5, g = e & 31;
                cpa16(sb + VTS_OFF + r * VT_PITCH + g * 16, &d_GXT[b][r][j0 + g * 8]);
            }
            cp_commit();
        }

        float acc[2][16][4];
        #pragma unroll
        for (int rt = 0; rt < 2; rt++)
            #pragma unroll
            for (int t = 0; t < 16; t++)
                #pragma unroll
                for (int q = 0; q < 4; q++) acc[rt][t][q] = 0.f;

        for (int c = 0; c < NCH; c++) {
            cp_wait0();
            __syncthreads();
            if (c + 1 < NCH) {
                uint32_t qb = sb + ((c + 1) & 1) * STAGE_BYTES;
                const int d0 = (c + 1) * KC;
                #pragma unroll
                for (int it = 0; it < 4; it++) {
                    int e = it * 256 + tid, r = e >> 3, g = e & 7;
                    cpa16(qb + sw128(r * 128 + g * 16), Mb + (size_t)(i0 + r) * DD + d0 + g * 8);
                }
                #pragma unroll
                for (int it = 0; it < 8; it++) {
                    int e = it * 256 + tid, r = e >> 3, g = e & 7;
                    cpa16(qb + KOFF + sw128(r * 128 + g * 16), Mb + (size_t)(j0 + r) * DD + d0 + g * 8);
                }
                cp_commit();
            }
            const uint32_t qb = sb + (c & 1) * STAGE_BYTES;
            const uint32_t kb = qb + KOFF;
            #pragma unroll
            for (int k16 = 0; k16 < 4; k16++) {
                uint32_t afr[2][4];
                ldsm4(afr[0], qb + sw128((wr * 32 + (lane & 15)) * 128 + k16 * 32 + (lane >> 4) * 16));
                ldsm4(afr[1], qb + sw128((wr * 32 + 16 + (lane & 15)) * 128 + k16 * 32 + (lane >> 4) * 16));
                #pragma unroll
                for (int nt = 0; nt < 8; nt++) {
                    uint32_t bfr[4];
                    ldsm4(bfr, kb + sw128((wc * 128 + nt * 16 + nl) * 128 + k16 * 32 + kh * 16));
                    mma_bf16(acc[0][2 * nt],     afr[0], bfr[0], bfr[1]);
                    mma_bf16(acc[0][2 * nt + 1], afr[0], bfr[2], bfr[3]);
                    mma_bf16(acc[1][2 * nt],     afr[1], bfr[0], bfr[1]);
                    mma_bf16(acc[1][2 * nt + 1], afr[1], bfr[2], bfr[3]);
                }
            }
        }

        // ---- row max ----
        float mxv[2][2];
        #pragma unroll
        for (int rt = 0; rt < 2; rt++) {
            float ma = -3.0e38f, mb2 = -3.0e38f;
            #pragma unroll
            for (int t = 0; t < 16; t++) {
                ma  = fmaxf(ma,  fmaxf(acc[rt][t][0], acc[rt][t][1]));
                mb2 = fmaxf(mb2, fmaxf(acc[rt][t][2], acc[rt][t][3]));
            }
            mxv[rt][0] = qredmax(ma);
            mxv[rt][1] = qredmax(mb2);
        }
        if ((lane & 3) == 0) {
            pm[wc * 128 + ra]      = mxv[0][0];
            pm[wc * 128 + ra + 8]  = mxv[0][1];
            pm[wc * 128 + ra + 16] = mxv[1][0];
            pm[wc * 128 + ra + 24] = mxv[1][1];
        }
        __syncthreads();
        if (tid < TMQ) {
            float mo = mr[tid];
            float mn = fmaxf(mo, fmaxf(pm[tid], pm[128 + tid]));
            scr[tid] = __expf(mo - mn);
            mr[tid] = mn;
        }
        __syncthreads();

        // ---- fused exp + PV (P stays in registers as A fragments) ----
        float mna[2], mnb[2], sca[2], scb[2];
        #pragma unroll
        for (int rt = 0; rt < 2; rt++) {
            mna[rt] = mr[ra + rt * 16];  mnb[rt] = mr[ra + rt * 16 + 8];
            sca[rt] = scr[ra + rt * 16]; scb[rt] = scr[ra + rt * 16 + 8];
        }
        #pragma unroll
        for (int rt = 0; rt < 2; rt++)
            #pragma unroll
            for (int ng = 0; ng < 4; ng++) {
                yacc[rt][ng][0] *= sca[rt]; yacc[rt][ng][1] *= sca[rt];
                yacc[rt][ng][2] *= scb[rt]; yacc[rt][ng][3] *= scb[rt];
            }
        float sa[2] = {0.f, 0.f}, sb2[2] = {0.f, 0.f};
        #pragma unroll
        for (int t = 0; t < 8; t++) {
            uint32_t bfr0[4], bfr1[4];
            ldsm4(bfr0, sb + VTS_OFF + nl * VT_PITCH        + wc * 256 + t * 32 + kh * 16);
            ldsm4(bfr1, sb + VTS_OFF + (16 + nl) * VT_PITCH + wc * 256 + t * 32 + kh * 16);
            #pragma unroll
            for (int rt = 0; rt < 2; rt++) {
                float e0 = __expf(acc[rt][2 * t][0] - mna[rt]);
                float e1 = __expf(acc[rt][2 * t][1] - mna[rt]);
                float e2 = __expf(acc[rt][2 * t][2] - mnb[rt]);
                float e3 = __expf(acc[rt][2 * t][3] - mnb[rt]);
                float e4 = __expf(acc[rt][2 * t + 1][0] - mna[rt]);
                float e5 = __expf(acc[rt][2 * t + 1][1] - mna[rt]);
                float e6 = __expf(acc[rt][2 * t + 1][2] - mnb[rt]);
                float e7 = __expf(acc[rt][2 * t + 1][3] - mnb[rt]);
                sa[rt]  += e0 + e1 + e4 + e5;
                sb2[rt] += e2 + e3 + e6 + e7;
                uint32_t a[4];
                __half2 h;
                h = __floats2half2_rn(e0, e1); a[0] = *(uint32_t*)&h;
                h = __floats2half2_rn(e2, e3); a[1] = *(uint32_t*)&h;
                h = __floats2half2_rn(e4, e5); a[2] = *(uint32_t*)&h;
                h = __floats2half2_rn(e6, e7); a[3] = *(uint32_t*)&h;
                mma_f16(yacc[rt][0], a, bfr0[0], bfr0[1]);
                mma_f16(yacc[rt][1], a, bfr0[2], bfr0[3]);
                mma_f16(yacc[rt][2], a, bfr1[0], bfr1[1]);
                mma_f16(yacc[rt][3], a, bfr1[2], bfr1[3]);
            }
        }
        #pragma unroll
        for (int rt = 0; rt < 2; rt++) { sa[rt] = qredsum(sa[rt]); sb2[rt] = qredsum(sb2[rt]); }
        if ((lane & 3) == 0) {
            psm[wc * 128 + ra]      = sa[0];
            psm[wc * 128 + ra + 8]  = sb2[0];
            psm[wc * 128 + ra + 16] = sa[1];
            psm[wc * 128 + ra + 24] = sb2[1];
        }
        __syncthreads();
        if (tid < TMQ) lr[tid] = lr[tid] * scr[tid] + psm[tid] + psm[128 + tid];
    }

    // ---- write split partials: combine wc halves, store O, m, l ----
    __syncthreads();
    float* yp = smf;   // [128][32], aliases stage0
    if (wc == 0) {
        #pragma unroll
        for (int rt = 0; rt < 2; rt++)
            #pragma unroll
            for (int ng = 0; ng < 4; ng++)
                #pragma unroll
                for (int q = 0; q < 4; q++) {
                    int row = wr * 32 + rt * 16 + (lane >> 2) + ((q & 2) ? 8 : 0);
                    int col = ng * 8 + (lane & 3) * 2 + (q & 1);
                    yp[row * 32 + col] = yacc[rt][ng][q];
                }
    }
    __syncthreads();
    const int sidx = b * SPLITS + split;
    if (wc == 1) {
        #pragma unroll
        for (int rt = 0; rt < 2; rt++)
            #pragma unroll
            for (int ng = 0; ng < 4; ng++)
                #pragma unroll
                for (int q = 0; q < 4; q++) {
                    int row = wr * 32 + rt * 16 + (lane >> 2) + ((q & 2) ? 8 : 0);
                    int col = ng * 8 + (lane & 3) * 2 + (q & 1);
                    d_part[sidx][i0 + row][col] = yp[row * 32 + col] + yacc[rt][ng][q];
                }
    }
    if (tid < TMQ) d_ml[sidx][i0 + tid] = make_float2(mr[tid], lr[tid]);
}

// ---------------- kernel 5: split combine + Ww conv + residual ----------------
// grid (NN/64, BB), 256 threads.
__global__ void combine_kernel(const float* __restrict__ x,
                               const float* __restrict__ Ww,
                               float* __restrict__ out) {
    const int b = blockIdx.y;
    const int r0 = blockIdx.x * 64;
    __shared__ float ysT[32][68];
    __shared__ float Ws[CC * IN];
    __shared__ float wA[64], wB[64];
    const int t = threadIdx.x;
    if (t < 64) {
        float2 ml0 = d_ml[b * SPLITS + 0][r0 + t];
        float2 ml1 = d_ml[b * SPLITS + 1][r0 + t];
        float m = fmaxf(ml0.x, ml1.x);
        float w0 = __expf(ml0.x - m), w1 = __expf(ml1.x - m);
        float inv = 1.f / (ml0.y * w0 + ml1.y * w1);
        wA[t] = w0 * inv; wB[t] = w1 * inv;
    }
    #pragma unroll
    for (int it = 0; it < 32; it++) Ws[it * 256 + t] = Ww[it * 256 + t];
    __syncthreads();
    for (int idx = t; idx < 64 * IN; idx += 256) {
        int rl = idx >> 5, col = idx & 31;
        ysT[col][rl] = d_part[b * SPLITS + 0][r0 + rl][col] * wA[rl]
                     + d_part[b * SPLITS + 1][r0 + rl][col] * wB[rl];
    }
    __syncthreads();

    const int r = t & 63;
    const int cg = t >> 6;
    float yreg[IN];
    #pragma unroll
    for (int i = 0; i < IN; i++) yreg[i] = ysT[i][r];
    const float* xb = x + (size_t)b * CC * NN;
    float* ob = out + (size_t)b * CC * NN;
    #pragma unroll 4
    for (int k = 0; k < 64; k++) {
        int c = cg * 64 + k;
        float s = 0.f;
        #pragma unroll
        for (int q = 0; q < 8; q++) {
            float4 w4 = *(const float4*)&Ws[c * 32 + q * 4];
            s += w4.x * yreg[q * 4] + w4.y * yreg[q * 4 + 1] + w4.z * yreg[q * 4 + 2] + w4.w * yreg[q * 4 + 3];
        }
        ob[(size_t)c * NN + r0 + r] = s + xb[(size_t)c * NN + r0 + r];
    }
}

extern "C" void kernel_launch(void* const* d_in, const int* in_sizes, int n_in,
                              void* d_out, int out_size) {
    const float* x  = (const float*)d_in[0];
    const float* Wg = (const float*)d_in[1];
    const float* Ww = (const float*)d_in[2];
    const float* W1 = (const float*)d_in[3];
    const float* W2 = (const float*)d_in[4];
    float* out = (float*)d_out;

    static int configured = 0;
    if (!configured) {
        cudaFuncSetAttribute(flash5_kernel, cudaFuncAttributeMaxDynamicSharedMemorySize, FLASH_SMEM);
        configured = 1;
    }

    pool_kernel<<<dim3(CC, BB), 256>>>(x);
    vcalc_kernel<<<1, 64>>>(W1, W2);
    split_kernel<<<dim3(NCH * (NN / 64), BB), 256>>>();
    gx_kernel<<<dim3(NN / 32, BB), 256>>>(x, Wg);
    flash5_kernel<<<dim3(NN / TMQ, SPLITS, BB), 256, FLASH_SMEM>>>();
    combine_kernel<<<dim3(NN / 64, BB), 256>>>(x, Ww, out);
}

// round 7
// speedup vs baseline: 12.1752x; 1.0102x over previous
#include <cuda_runtime.h>
#include <cuda_bf16.h>
#include <cuda_fp16.h>
#include <cstdint>

// Problem constants
#define BB 2
#define CC 256
#define NN 4096          // 64*64
#define DD 768           // 3*CC
#define IN 32            // inter

// Flash tiling
#define TMQ 128          // q rows per block
#define TNK 256          // keys per j-tile
#define KC 64            // feature chunk (=128B bf16 row)
#define NCH (DD / KC)    // 12
#define SPLITS 2
#define KEYS (NN / SPLITS)   // 2048
#define NJT (KEYS / TNK)     // 8

// SMEM layout (bytes) for flash
#define QBYTES 16384           // 128 x 64 bf16
#define KOFF   16384
#define STAGE_BYTES 49152      // Q 16K + K 32K
#define VTS_OFF 98304          // fp16 VT [32][272] (pitch 544B)
#define VT_PITCH 544
#define PM_OFF   115712        // fp32 [2][128]
#define PSUM_OFF 116736        // fp32 [2][128]
#define MR_OFF   117760        // fp32 [128]
#define LR_OFF   118272
#define SCR_OFF  118784
#define FLASH_SMEM 119296

// Scratch (static device globals; no allocation)
__device__ float d_M[BB][2 * CC][NN];                     // pooled variants 3,5 only (fp32)
__device__ __align__(16) __nv_bfloat16 d_Mt[BB][NN][DD];  // token-major, scaled, bf16
__device__ __align__(16) __half d_GXT[BB][IN][NN];        // g_x as [b][i][n], fp16
__device__ float d_S[3][BB][CC];
__device__ float d_sqrtV[BB][3];
__device__ float d_part[BB * SPLITS][NN][IN];             // split partial O (unnormalized)
__device__ float2 d_ml[BB * SPLITS][NN];                  // split (m, l)

// ---------------- helpers ----------------
__device__ __forceinline__ uint32_t smem_u32(const void* p) {
    uint32_t a;
    asm("{ .reg .u64 t; cvta.to.shared.u64 t, %1; cvt.u32.u64 %0, t; }" : "=r"(a) : "l"(p));
    return a;
}
__device__ __forceinline__ uint32_t sw128(uint32_t bo) { return bo ^ ((bo >> 3) & 0x70); }

__device__ __forceinline__ void cpa16(uint32_t dst, const void* src) {
    asm volatile("cp.async.cg.shared.global [%0], [%1], 16;" :: "r"(dst), "l"(src));
}
__device__ __forceinline__ void cp_commit() { asm volatile("cp.async.commit_group;"); }
__device__ __forceinline__ void cp_wait0() { asm volatile("cp.async.wait_group 0;"); }
__device__ __forceinline__ void cp_wait1() { asm volatile("cp.async.wait_group 1;"); }

__device__ __forceinline__ void ldsm4(uint32_t* r, uint32_t addr) {
    asm volatile("ldmatrix.sync.aligned.m8n8.x4.shared.b16 {%0,%1,%2,%3}, [%4];"
                 : "=r"(r[0]), "=r"(r[1]), "=r"(r[2]), "=r"(r[3]) : "r"(addr));
}
__device__ __forceinline__ void mma_bf16(float* c, const uint32_t* a, uint32_t b0, uint32_t b1) {
    asm volatile("mma.sync.aligned.m16n8k16.row.col.f32.bf16.bf16.f32 "
                 "{%0,%1,%2,%3},{%4,%5,%6,%7},{%8,%9},{%0,%1,%2,%3};"
                 : "+f"(c[0]), "+f"(c[1]), "+f"(c[2]), "+f"(c[3])
                 : "r"(a[0]), "r"(a[1]), "r"(a[2]), "r"(a[3]), "r"(b0), "r"(b1));
}
__device__ __forceinline__ void mma_f16(float* c, const uint32_t* a, uint32_t b0, uint32_t b1) {
    asm volatile("mma.sync.aligned.m16n8k16.row.col.f32.f16.f16.f32 "
                 "{%0,%1,%2,%3},{%4,%5,%6,%7},{%8,%9},{%0,%1,%2,%3};"
                 : "+f"(c[0]), "+f"(c[1]), "+f"(c[2]), "+f"(c[3])
                 : "r"(a[0]), "r"(a[1]), "r"(a[2]), "r"(a[3]), "r"(b0), "r"(b1));
}
__device__ __forceinline__ float qredmax(float v) {
    v = fmaxf(v, __shfl_xor_sync(0xffffffffu, v, 1));
    v = fmaxf(v, __shfl_xor_sync(0xffffffffu, v, 2));
    return v;
}
__device__ __forceinline__ float qredsum(float v) {
    v += __shfl_xor_sync(0xffffffffu, v, 1);
    v += __shfl_xor_sync(0xffffffffu, v, 2);
    return v;
}

// ---------------- kernel 1: pooling + channel sums (writes pooled variants only) ----------------
__global__ void pool_kernel(const float* __restrict__ x) {
    const int c = blockIdx.x, b = blockIdx.y;
    const float* xp = x + ((size_t)(b * CC + c)) * NN;
    __shared__ float xs[64][64];
    __shared__ float h3[64][64];
    __shared__ float h5[64][64];
    const int t = threadIdx.x;

    for (int p = t; p < NN; p += 256) xs[p >> 6][p & 63] = xp[p];
    __syncthreads();
    for (int p = t; p < NN; p += 256) {
        int h = p >> 6, w = p & 63;
        float c0 = xs[h][w];
        float l1 = (w > 0)  ? xs[h][w - 1] : 0.f;
        float r1 = (w < 63) ? xs[h][w + 1] : 0.f;
        float l2 = (w > 1)  ? xs[h][w - 2] : 0.f;
        float r2 = (w < 62) ? xs[h][w + 2] : 0.f;
        h3[h][w] = l1 + c0 + r1;
        h5[h][w] = l2 + l1 + c0 + r1 + r2;
    }
    __syncthreads();
    float s1 = 0.f, s3 = 0.f, s5 = 0.f;
    float* M3 = &d_M[b][c][0];
    float* M5 = &d_M[b][CC + c][0];
    for (int p = t; p < NN; p += 256) {
        int h = p >> 6, w = p & 63;
        float v0 = xs[h][w];
        float u1 = (h > 0)  ? h3[h - 1][w] : 0.f;
        float dn1 = (h < 63) ? h3[h + 1][w] : 0.f;
        float u2 = (h > 1)  ? h5[h - 2][w] : 0.f;
        float dn2 = (h < 62) ? h5[h + 2][w] : 0.f;
        float u1b = (h > 0)  ? h5[h - 1][w] : 0.f;
        float dn1b = (h < 63) ? h5[h + 1][w] : 0.f;
        float p3 = (u1 + h3[h][w] + dn1) * (1.f / 9.f);
        float p5 = (u2 + u1b + h5[h][w] + dn1b + dn2) * (1.f / 25.f);
        M3[p] = p3; M5[p] = p5;
        s1 += v0; s3 += p3; s5 += p5;
    }
    __syncthreads();
    float* r1 = &xs[0][0];
    float* r3 = &h3[0][0];
    float* r5 = &h5[0][0];
    r1[t] = s1; r3[t] = s3; r5[t] = s5;
    __syncthreads();
    for (int off = 128; off > 0; off >>= 1) {
        if (t < off) { r1[t] += r1[t + off]; r3[t] += r3[t + off]; r5[t] += r5[t + off]; }
        __syncthreads();
    }
    if (t == 0) {
        d_S[0][b][c] = r1[0];
        d_S[1][b][c] = r3[0];
        d_S[2][b][c] = r5[0];
    }
}

// ---------------- kernel 2: tiny V computation ----------------
__global__ void vcalc_kernel(const float* __restrict__ W1, const float* __restrict__ W2) {
    __shared__ float m[BB][3];
    const int t = threadIdx.x;
    if (t < 6) {
        int k = t % 3, b = t / 3;
        float s = 0.f;
        for (int c = 0; c < CC; c++) { float v = d_S[k][b][c]; s += v * v; }
        m[b][k] = s * (1.f / ((float)NN * (float)NN));
    }
    __syncthreads();
    if (t < BB) {
        int b = t;
        float h[16];
        #pragma unroll
        for (int i = 0; i < 16; i++)
            h[i] = W1[i * 3 + 0] * m[b][0] + W1[i * 3 + 1] * m[b][1] + W1[i * 3 + 2] * m[b][2];
        float o[3];
        #pragma unroll
        for (int j = 0; j < 3; j++) {
            float s = 0.f;
            #pragma unroll
            for (int i = 0; i < 16; i++) s += W2[j * 16 + i] * h[i];
            o[j] = s;
        }
        float mx = fmaxf(o[0], fmaxf(o[1], o[2]));
        float e0 = expf(o[0] - mx), e1 = expf(o[1] - mx), e2 = expf(o[2] - mx);
        float inv = 1.f / (e0 + e1 + e2);
        d_sqrtV[b][0] = sqrtf(e0 * inv);
        d_sqrtV[b][1] = sqrtf(e1 * inv);
        d_sqrtV[b][2] = sqrtf(e2 * inv);
    }
}

// ---------------- kernel 2b: transpose + scale + bf16 convert ----------------
// variant 0 reads x directly; variants 1,2 read d_M.
__global__ void split_kernel(const float* __restrict__ x) {
    const int b = blockIdx.y;
    const int dtile = blockIdx.x % NCH;
    const int ntile = blockIdx.x / NCH;
    const int d0 = dtile * 64, n0 = ntile * 64;
    const float s = d_sqrtV[b][dtile >> 2];
    const float* src = (dtile < 4) ? (x + ((size_t)b * CC + d0) * NN)
                                   : &d_M[b][d0 - CC][0];
    __shared__ float sme[64][65];
    const int t = threadIdx.x;
    #pragma unroll
    for (int it = 0; it < 4; it++) {
        int e = it * 256 + t;
        int r = e >> 4, c4 = (e & 15) << 2;
        float4 v = *(const float4*)&src[(size_t)r * NN + n0 + c4];
        sme[r][c4] = v.x; sme[r][c4 + 1] = v.y; sme[r][c4 + 2] = v.z; sme[r][c4 + 3] = v.w;
    }
    __syncthreads();
    #pragma unroll
    for (int it = 0; it < 2; it++) {
        int e = it * 256 + t;
        int r2 = e >> 3, g = e & 7;
        __nv_bfloat16 hv[8];
        #pragma unroll
        for (int q = 0; q < 8; q++)
            hv[q] = __float2bfloat16(sme[g * 8 + q][r2] * s);
        *(uint4*)&d_Mt[b][n0 + r2][d0 + g * 8] = *(uint4*)hv;
    }
}

// ---------------- kernel 3: g_x^T = (Wg @ x) as [b][i][n], fp16 ----------------
// grid (NN/32 = 128, 2), block 256. cp.async 3-buffer pipeline over 8 x-chunks of 32 channels.
__global__ void gx_kernel(const float* __restrict__ x, const float* __restrict__ Wg) {
    const int b = blockIdx.y;
    const int n0 = blockIdx.x * 32;
    __shared__ float Wgs[256][33];       // [c][i], padded
    __shared__ __align__(16) float xsb[3][32 * 32];  // 3-stage x chunks
    const uint32_t xsb_u = smem_u32(xsb);
    const int t = threadIdx.x;
    const int i = t & 31, ng = t >> 5;
    const float* xb = x + (size_t)b * CC * NN;

    // prefetch chunk 0
    {
        int r = t >> 3, q = t & 7;
        cpa16(xsb_u + (r * 32 + q * 4) * 4, &xb[(size_t)r * NN + n0 + q * 4]);
        cp_commit();
    }
    // stage whole Wg (transposed) — covered by the first barrier
    #pragma unroll
    for (int it = 0; it < 32; it++) {
        int e = it * 256 + t;
        int ii = e >> 8, cc = e & 255;
        Wgs[cc][ii] = Wg[ii * CC + cc];
    }

    float acc[4] = {0.f, 0.f, 0.f, 0.f};
    for (int c = 0; c < 8; c++) {
        if (c + 1 < 8) {
            int r = t >> 3, q = t & 7;
            cpa16(xsb_u + (((c + 1) % 3) * 1024 + r * 32 + q * 4) * 4,
                  &xb[(size_t)((c + 1) * 32 + r) * NN + n0 + q * 4]);
            cp_commit();
            cp_wait1();
        } else {
            cp_wait0();
        }
        __syncthreads();
        const float* xs = &xsb[c % 3][0];
        const int cbase = c * 32;
        #pragma unroll
        for (int cc = 0; cc < 32; cc++) {
            float w = Wgs[cbase + cc][i];
            float4 xv = *(const float4*)&xs[cc * 32 + ng * 4];
            acc[0] += w * xv.x; acc[1] += w * xv.y; acc[2] += w * xv.z; acc[3] += w * xv.w;
        }
    }
    __half hv[4];
    #pragma unroll
    for (int j = 0; j < 4; j++) hv[j] = __float2half(acc[j]);
    *(uint2*)&d_GXT[b][i][n0 + ng * 4] = *(uint2*)hv;
}

// ---------------- kernel 4: split-K mma.sync flash attention ----------------
// grid (NN/TMQ=32, SPLITS, BB), 256 threads (8 warps).
__global__ __launch_bounds__(256, 1) void flash5_kernel() {
    extern __shared__ __align__(16) char sm[];
    float* smf = (float*)sm;
    const uint32_t sb = smem_u32(sm);
    const int tid = threadIdx.x, warp = tid >> 5, lane = tid & 31;
    const int i0 = blockIdx.x * TMQ;
    const int split = blockIdx.y;
    const int b = blockIdx.z;
    const int wr = warp >> 1, wc = warp & 1;

    float* pm  = smf + PM_OFF / 4;     // [2][128]
    float* psm = smf + PSUM_OFF / 4;   // [2][128]
    float* mr  = smf + MR_OFF / 4;
    float* lr  = smf + LR_OFF / 4;
    float* scr = smf + SCR_OFF / 4;

    if (tid < TMQ) { mr[tid] = -3.0e38f; lr[tid] = 0.f; }
    __syncthreads();

    const int nl = (lane & 7) | ((lane & 16) >> 1);
    const int kh = (lane >> 3) & 1;
    const int ra = wr * 32 + (lane >> 2);

    float yacc[2][4][4];
    #pragma unroll
    for (int rt = 0; rt < 2; rt++)
        #pragma unroll
        for (int ng = 0; ng < 4; ng++)
            #pragma unroll
            for (int q = 0; q < 4; q++) yacc[rt][ng][q] = 0.f;

    const __nv_bfloat16* Mb = &d_Mt[b][0][0];

    for (int jt = 0; jt < NJT; jt++) {
        const int j0 = split * KEYS + jt * TNK;

        // prologue: chunk 0 (stage 0) + VT tile
        {
            uint32_t qb = sb;
            #pragma unroll
            for (int it = 0; it < 4; it++) {
                int e = it * 256 + tid, r = e >> 3, g = e & 7;
                cpa16(qb + sw128(r * 128 + g * 16), Mb + (size_t)(i0 + r) * DD + g * 8);
            }
            #pragma unroll
            for (int it = 0; it < 8; it++) {
                int e = it * 256 + tid, r = e >> 3, g = e & 7;
                cpa16(qb + KOFF + sw128(r * 128 + g * 16), Mb + (size_t)(j0 + r) * DD + g * 8);
            }
            #pragma unroll
            for (int it = 0; it < 4; it++) {
                int e = it * 256 + tid, r = e >> 5, g = e & 31;
                cpa16(sb + VTS_OFF + r * VT_PITCH + g * 16, &d_GXT[b][r][j0 + g * 8]);
            }
            cp_commit();
        }

        float acc[2][16][4];
        #pragma unroll
        for (int rt = 0; rt < 2; rt++)
            #pragma unroll
            for (int t = 0; t < 16; t++)
                #pragma unroll
                for (int q = 0; q < 4; q++) acc[rt][t][q] = 0.f;

        for (int c = 0; c < NCH; c++) {
            cp_wait0();
            __syncthreads();
            if (c + 1 < NCH) {
                uint32_t qb = sb + ((c + 1) & 1) * STAGE_BYTES;
                const int d0 = (c + 1) * KC;
                #pragma unroll
                for (int it = 0; it < 4; it++) {
                    int e = it * 256 + tid, r = e >> 3, g = e & 7;
                    cpa16(qb + sw128(r * 128 + g * 16), Mb + (size_t)(i0 + r) * DD + d0 + g * 8);
                }
                #pragma unroll
                for (int it = 0; it < 8; it++) {
                    int e = it * 256 + tid, r = e >> 3, g = e & 7;
                    cpa16(qb + KOFF + sw128(r * 128 + g * 16), Mb + (size_t)(j0 + r) * DD + d0 + g * 8);
                }
                cp_commit();
            }
            const uint32_t qb = sb + (c & 1) * STAGE_BYTES;
            const uint32_t kb = qb + KOFF;
            #pragma unroll
            for (int k16 = 0; k16 < 4; k16++) {
                uint32_t afr[2][4];
                ldsm4(afr[0], qb + sw128((wr * 32 + (lane & 15)) * 128 + k16 * 32 + (lane >> 4) * 16));
                ldsm4(afr[1], qb + sw128((wr * 32 + 16 + (lane & 15)) * 128 + k16 * 32 + (lane >> 4) * 16));
                #pragma unroll
                for (int nt = 0; nt < 8; nt++) {
                    uint32_t bfr[4];
                    ldsm4(bfr, kb + sw128((wc * 128 + nt * 16 + nl) * 128 + k16 * 32 + kh * 16));
                    mma_bf16(acc[0][2 * nt],     afr[0], bfr[0], bfr[1]);
                    mma_bf16(acc[0][2 * nt + 1], afr[0], bfr[2], bfr[3]);
                    mma_bf16(acc[1][2 * nt],     afr[1], bfr[0], bfr[1]);
                    mma_bf16(acc[1][2 * nt + 1], afr[1], bfr[2], bfr[3]);
                }
            }
        }

        // ---- row max ----
        float mxv[2][2];
        #pragma unroll
        for (int rt = 0; rt < 2; rt++) {
            float ma = -3.0e38f, mb2 = -3.0e38f;
            #pragma unroll
            for (int t = 0; t < 16; t++) {
                ma  = fmaxf(ma,  fmaxf(acc[rt][t][0], acc[rt][t][1]));
                mb2 = fmaxf(mb2, fmaxf(acc[rt][t][2], acc[rt][t][3]));
            }
            mxv[rt][0] = qredmax(ma);
            mxv[rt][1] = qredmax(mb2);
        }
        if ((lane & 3) == 0) {
            pm[wc * 128 + ra]      = mxv[0][0];
            pm[wc * 128 + ra + 8]  = mxv[0][1];
            pm[wc * 128 + ra + 16] = mxv[1][0];
            pm[wc * 128 + ra + 24] = mxv[1][1];
        }
        __syncthreads();
        if (tid < TMQ) {
            float mo = mr[tid];
            float mn = fmaxf(mo, fmaxf(pm[tid], pm[128 + tid]));
            scr[tid] = __expf(mo - mn);
            mr[tid] = mn;
        }
        __syncthreads();

        // ---- fused exp + PV (P stays in registers as A fragments) ----
        float mna[2], mnb[2], sca[2], scb[2];
        #pragma unroll
        for (int rt = 0; rt < 2; rt++) {
            mna[rt] = mr[ra + rt * 16];  mnb[rt] = mr[ra + rt * 16 + 8];
            sca[rt] = scr[ra + rt * 16]; scb[rt] = scr[ra + rt * 16 + 8];
        }
        #pragma unroll
        for (int rt = 0; rt < 2; rt++)
            #pragma unroll
            for (int ng = 0; ng < 4; ng++) {
                yacc[rt][ng][0] *= sca[rt]; yacc[rt][ng][1] *= sca[rt];
                yacc[rt][ng][2] *= scb[rt]; yacc[rt][ng][3] *= scb[rt];
            }
        float sa[2] = {0.f, 0.f}, sb2[2] = {0.f, 0.f};
        #pragma unroll
        for (int t = 0; t < 8; t++) {
            uint32_t bfr0[4], bfr1[4];
            ldsm4(bfr0, sb + VTS_OFF + nl * VT_PITCH        + wc * 256 + t * 32 + kh * 16);
            ldsm4(bfr1, sb + VTS_OFF + (16 + nl) * VT_PITCH + wc * 256 + t * 32 + kh * 16);
            #pragma unroll
            for (int rt = 0; rt < 2; rt++) {
                float e0 = __expf(acc[rt][2 * t][0] - mna[rt]);
                float e1 = __expf(acc[rt][2 * t][1] - mna[rt]);
                float e2 = __expf(acc[rt][2 * t][2] - mnb[rt]);
                float e3 = __expf(acc[rt][2 * t][3] - mnb[rt]);
                float e4 = __expf(acc[rt][2 * t + 1][0] - mna[rt]);
                float e5 = __expf(acc[rt][2 * t + 1][1] - mna[rt]);
                float e6 = __expf(acc[rt][2 * t + 1][2] - mnb[rt]);
                float e7 = __expf(acc[rt][2 * t + 1][3] - mnb[rt]);
                sa[rt]  += e0 + e1 + e4 + e5;
                sb2[rt] += e2 + e3 + e6 + e7;
                uint32_t a[4];
                __half2 h;
                h = __floats2half2_rn(e0, e1); a[0] = *(uint32_t*)&h;
                h = __floats2half2_rn(e2, e3); a[1] = *(uint32_t*)&h;
                h = __floats2half2_rn(e4, e5); a[2] = *(uint32_t*)&h;
                h = __floats2half2_rn(e6, e7); a[3] = *(uint32_t*)&h;
                mma_f16(yacc[rt][0], a, bfr0[0], bfr0[1]);
                mma_f16(yacc[rt][1], a, bfr0[2], bfr0[3]);
                mma_f16(yacc[rt][2], a, bfr1[0], bfr1[1]);
                mma_f16(yacc[rt][3], a, bfr1[2], bfr1[3]);
            }
        }
        #pragma unroll
        for (int rt = 0; rt < 2; rt++) { sa[rt] = qredsum(sa[rt]); sb2[rt] = qredsum(sb2[rt]); }
        if ((lane & 3) == 0) {
            psm[wc * 128 + ra]      = sa[0];
            psm[wc * 128 + ra + 8]  = sb2[0];
            psm[wc * 128 + ra + 16] = sa[1];
            psm[wc * 128 + ra + 24] = sb2[1];
        }
        __syncthreads();
        if (tid < TMQ) lr[tid] = lr[tid] * scr[tid] + psm[tid] + psm[128 + tid];
    }

    // ---- write split partials: combine wc halves, store O, m, l ----
    __syncthreads();
    float* yp = smf;   // [128][32], aliases stage0
    if (wc == 0) {
        #pragma unroll
        for (int rt = 0; rt < 2; rt++)
            #pragma unroll
            for (int ng = 0; ng < 4; ng++)
                #pragma unroll
                for (int q = 0; q < 4; q++) {
                    int row = wr * 32 + rt * 16 + (lane >> 2) + ((q & 2) ? 8 : 0);
                    int col = ng * 8 + (lane & 3) * 2 + (q & 1);
                    yp[row * 32 + col] = yacc[rt][ng][q];
                }
    }
    __syncthreads();
    const int sidx = b * SPLITS + split;
    if (wc == 1) {
        #pragma unroll
        for (int rt = 0; rt < 2; rt++)
            #pragma unroll
            for (int ng = 0; ng < 4; ng++)
                #pragma unroll
                for (int q = 0; q < 4; q++) {
                    int row = wr * 32 + rt * 16 + (lane >> 2) + ((q & 2) ? 8 : 0);
                    int col = ng * 8 + (lane & 3) * 2 + (q & 1);
                    d_part[sidx][i0 + row][col] = yp[row * 32 + col] + yacc[rt][ng][q];
                }
    }
    if (tid < TMQ) d_ml[sidx][i0 + tid] = make_float2(mr[tid], lr[tid]);
}

// ---------------- kernel 5: split combine + Ww conv + residual ----------------
__global__ void combine_kernel(const float* __restrict__ x,
                               const float* __restrict__ Ww,
                               float* __restrict__ out) {
    const int b = blockIdx.y;
    const int r0 = blockIdx.x * 64;
    __shared__ float ysT[32][68];
    __shared__ float Ws[CC * IN];
    __shared__ float wA[64], wB[64];
    const int t = threadIdx.x;
    if (t < 64) {
        float2 ml0 = d_ml[b * SPLITS + 0][r0 + t];
        float2 ml1 = d_ml[b * SPLITS + 1][r0 + t];
        float m = fmaxf(ml0.x, ml1.x);
        float w0 = __expf(ml0.x - m), w1 = __expf(ml1.x - m);
        float inv = 1.f / (ml0.y * w0 + ml1.y * w1);
        wA[t] = w0 * inv; wB[t] = w1 * inv;
    }
    #pragma unroll
    for (int it = 0; it < 32; it++) Ws[it * 256 + t] = Ww[it * 256 + t];
    __syncthreads();
    for (int idx = t; idx < 64 * IN; idx += 256) {
        int rl = idx >> 5, col = idx & 31;
        ysT[col][rl] = d_part[b * SPLITS + 0][r0 + rl][col] * wA[rl]
                     + d_part[b * SPLITS + 1][r0 + rl][col] * wB[rl];
    }
    __syncthreads();

    const int r = t & 63;
    const int cg = t >> 6;
    float yreg[IN];
    #pragma unroll
    for (int i = 0; i < IN; i++) yreg[i] = ysT[i][r];
    const float* xb = x + (size_t)b * CC * NN;
    float* ob = out + (size_t)b * CC * NN;
    #pragma unroll 4
    for (int k = 0; k < 64; k++) {
        int c = cg * 64 + k;
        float s = 0.f;
        #pragma unroll
        for (int q = 0; q < 8; q++) {
            float4 w4 = *(const float4*)&Ws[c * 32 + q * 4];
            s += w4.x * yreg[q * 4] + w4.y * yreg[q * 4 + 1] + w4.z * yreg[q * 4 + 2] + w4.w * yreg[q * 4 + 3];
        }
        ob[(size_t)c * NN + r0 + r] = s + xb[(size_t)c * NN + r0 + r];
    }
}

extern "C" void kernel_launch(void* const* d_in, const int* in_sizes, int n_in,
                              void* d_out, int out_size) {
    const float* x  = (const float*)d_in[0];
    const float* Wg = (const float*)d_in[1];
    const float* Ww = (const float*)d_in[2];
    const float* W1 = (const float*)d_in[3];
    const float* W2 = (const float*)d_in[4];
    float* out = (float*)d_out;

    static int configured = 0;
    if (!configured) {
        cudaFuncSetAttribute(flash5_kernel, cudaFuncAttributeMaxDynamicSharedMemorySize, FLASH_SMEM);
        configured = 1;
    }

    pool_kernel<<<dim3(CC, BB), 256>>>(x);
    vcalc_kernel<<<1, 64>>>(W1, W2);
    split_kernel<<<dim3(NCH * (NN / 64), BB), 256>>>(x);
    gx_kernel<<<dim3(NN / 32, BB), 256>>>(x, Wg);
    flash5_kernel<<<dim3(NN / TMQ, SPLITS, BB), 256, FLASH_SMEM>>>();
    combine_kernel<<<dim3(NN / 64, BB), 256>>>(x, Ww, out);
}